// round 1
// baseline (speedup 1.0000x reference)
#include <cuda_runtime.h>
#include <cuda_bf16.h>
#include <cstddef>

// Problem constants
#define TB 2
#define TT 2048
#define TC 1024
#define TH 16
#define TD 64

// Scratch (allocation-free rule: __device__ globals)
__device__ float g_qkv[(size_t)TB * TT * 3 * TC];   // [B,T,3C]  ~50 MB
__device__ float g_attn[(size_t)TB * TT * TC];      // [B,T,C]   ~17 MB

// ---------------------------------------------------------------------------
// Tiled SGEMM: C[M,N] = A[M,K] @ B[K,N], all row-major, fp32.
// BM=BN=128, BK=16, 256 threads, 8x8 per-thread microtile.
// Assumes M%128==0, N%128==0, K%16==0 (true for all three calls).
// ---------------------------------------------------------------------------
#define BM 128
#define BN 128
#define BK 16

__global__ __launch_bounds__(256) void sgemm_kernel(
    const float* __restrict__ A, const float* __restrict__ B,
    float* __restrict__ C, int M, int N, int K)
{
    __shared__ float As[BK][BM];
    __shared__ float Bs[BK][BN];

    const int tid = threadIdx.x;
    const int tx = tid & 15;        // 0..15
    const int ty = tid >> 4;        // 0..15
    const int row0 = blockIdx.y * BM;
    const int col0 = blockIdx.x * BN;

    float acc[8][8];
    #pragma unroll
    for (int i = 0; i < 8; i++)
        #pragma unroll
        for (int j = 0; j < 8; j++) acc[i][j] = 0.f;

    for (int k0 = 0; k0 < K; k0 += BK) {
        // Load A tile (transposed into As) and B tile; 512 float4 each, 2 per thread
        #pragma unroll
        for (int it = 0; it < 2; it++) {
            int idx = tid + it * 256;              // 0..511
            int ar = idx >> 2;                     // 0..127
            int ac = (idx & 3) << 2;               // 0,4,8,12
            float4 va = *(const float4*)(A + (size_t)(row0 + ar) * K + k0 + ac);
            As[ac + 0][ar] = va.x; As[ac + 1][ar] = va.y;
            As[ac + 2][ar] = va.z; As[ac + 3][ar] = va.w;
            int br = idx >> 5;                     // 0..15
            int bc = (idx & 31) << 2;              // 0..124
            *(float4*)(&Bs[br][bc]) =
                *(const float4*)(B + (size_t)(k0 + br) * N + col0 + bc);
        }
        __syncthreads();

        #pragma unroll
        for (int k = 0; k < BK; k++) {
            float af[8], bf[8];
            #pragma unroll
            for (int i = 0; i < 8; i += 4)
                *(float4*)(af + i) = *(const float4*)(&As[k][ty * 8 + i]);
            #pragma unroll
            for (int j = 0; j < 8; j += 4)
                *(float4*)(bf + j) = *(const float4*)(&Bs[k][tx * 8 + j]);
            #pragma unroll
            for (int i = 0; i < 8; i++)
                #pragma unroll
                for (int j = 0; j < 8; j++)
                    acc[i][j] = fmaf(af[i], bf[j], acc[i][j]);
        }
        __syncthreads();
    }

    #pragma unroll
    for (int i = 0; i < 8; i++) {
        float* cp = C + (size_t)(row0 + ty * 8 + i) * N + col0 + tx * 8;
        *(float4*)(cp)     = make_float4(acc[i][0], acc[i][1], acc[i][2], acc[i][3]);
        *(float4*)(cp + 4) = make_float4(acc[i][4], acc[i][5], acc[i][6], acc[i][7]);
    }
}

// ---------------------------------------------------------------------------
// Flash attention (causal), fp32.
// grid = (T/128, B*H), block = 128 threads. One thread = one query row.
// K/V tiles of 64 rows staged in SMEM; online softmax in 16-key chunks
// (keeps s[] in registers with constant indices; regs ~180, no spill).
// ---------------------------------------------------------------------------
__global__ __launch_bounds__(128) void attn_kernel(
    const float* __restrict__ qkv, float* __restrict__ out)
{
    __shared__ float Ks[64 * TD];
    __shared__ float Vs[64 * TD];

    const int b = blockIdx.y >> 4;
    const int h = blockIdx.y & 15;
    const int r = blockIdx.x * 128 + threadIdx.x;   // query row (0..T-1)
    const size_t rowstride = 3 * TC;

    // Load q row into registers
    float q[TD];
    {
        const float* qp = qkv + ((size_t)b * TT + r) * rowstride + h * TD;
        #pragma unroll
        for (int d = 0; d < TD; d += 4) {
            float4 v4 = *(const float4*)(qp + d);
            q[d] = v4.x; q[d + 1] = v4.y; q[d + 2] = v4.z; q[d + 3] = v4.w;
        }
    }

    float o[TD];
    #pragma unroll
    for (int d = 0; d < TD; d++) o[d] = 0.f;
    float m = -3.0e38f, l = 0.f;

    const int kend = blockIdx.x * 128 + 128;  // exclusive key bound for this block

    #pragma unroll 1
    for (int j0 = 0; j0 < kend; j0 += 64) {
        __syncthreads();
        // Stage K and V tiles: 64 rows x 64 dims, 1024 float4 each / 128 threads
        #pragma unroll
        for (int i = 0; i < 8; i++) {
            int idx = threadIdx.x + i * 128;   // 0..1023
            int row = idx >> 4;
            int cv  = (idx & 15) << 2;
            const float* kp = qkv + ((size_t)b * TT + j0 + row) * rowstride
                              + TC + h * TD + cv;
            *(float4*)(Ks + row * TD + cv) = *(const float4*)kp;
            *(float4*)(Vs + row * TD + cv) = *(const float4*)(kp + TC);
        }
        __syncthreads();

        #pragma unroll 1
        for (int jc = 0; jc < 4; jc++) {
            float s[16];
            float mt = m;
            #pragma unroll
            for (int jj = 0; jj < 16; jj++) {
                const int j = jc * 16 + jj;
                float acc = 0.f;
                const float* kk = Ks + j * TD;
                #pragma unroll
                for (int d = 0; d < TD; d += 4) {
                    float4 k4 = *(const float4*)(kk + d);
                    acc = fmaf(q[d],     k4.x, acc);
                    acc = fmaf(q[d + 1], k4.y, acc);
                    acc = fmaf(q[d + 2], k4.z, acc);
                    acc = fmaf(q[d + 3], k4.w, acc);
                }
                acc *= 0.125f;                       // 1/sqrt(64)
                if (j0 + j > r) acc = -1e30f;        // causal mask
                s[jj] = acc;
                mt = fmaxf(mt, acc);
            }
            float resc = __expf(m - mt);
            m = mt;
            l *= resc;
            #pragma unroll
            for (int d = 0; d < TD; d++) o[d] *= resc;
            #pragma unroll
            for (int jj = 0; jj < 16; jj++) {
                float p = __expf(s[jj] - m);
                l += p;
                const float* vv = Vs + (jc * 16 + jj) * TD;
                #pragma unroll
                for (int d = 0; d < TD; d += 4) {
                    float4 v4 = *(const float4*)(vv + d);
                    o[d]     = fmaf(p, v4.x, o[d]);
                    o[d + 1] = fmaf(p, v4.y, o[d + 1]);
                    o[d + 2] = fmaf(p, v4.z, o[d + 2]);
                    o[d + 3] = fmaf(p, v4.w, o[d + 3]);
                }
            }
        }
    }

    const float inv = 1.f / l;
    float* op = out + ((size_t)b * TT + r) * TC + h * TD;
    #pragma unroll
    for (int d = 0; d < TD; d += 4)
        *(float4*)(op + d) = make_float4(o[d] * inv, o[d + 1] * inv,
                                         o[d + 2] * inv, o[d + 3] * inv);
}

// ---------------------------------------------------------------------------
extern "C" void kernel_launch(void* const* d_in, const int* in_sizes, int n_in,
                              void* d_out, int out_size)
{
    const float* x    = (const float*)d_in[0];   // [B,T,C]
    const float* Wqkv = (const float*)d_in[1];   // [C,3C]
    const float* Wout = (const float*)d_in[2];   // [C,C]
    float* out = (float*)d_out;                  // [B,T,C]

    float *qkv_ptr, *attn_ptr;
    cudaGetSymbolAddress((void**)&qkv_ptr, g_qkv);
    cudaGetSymbolAddress((void**)&attn_ptr, g_attn);

    const int M = TB * TT;   // 4096

    // 1) QKV projection: [4096,1024] @ [1024,3072]
    sgemm_kernel<<<dim3((3 * TC) / BN, M / BM), 256>>>(x, Wqkv, qkv_ptr, M, 3 * TC, TC);

    // 2) Causal flash attention
    attn_kernel<<<dim3(TT / 128, TB * TH), 128>>>(qkv_ptr, attn_ptr);

    // 3) Output projection: [4096,1024] @ [1024,1024]
    sgemm_kernel<<<dim3(TC / BN, M / BM), 256>>>(attn_ptr, Wout, out, M, TC, TC);
}

// round 2
// speedup vs baseline: 1.3529x; 1.3529x over previous
#include <cuda_runtime.h>
#include <cuda_bf16.h>
#include <cstdint>
#include <cstddef>

// Problem constants
#define TB 2
#define TT 2048
#define TC 1024
#define TH 16
#define TD 64

// ---------------------------------------------------------------------------
// Scratch (__device__ globals; allocation-free rule)
// ---------------------------------------------------------------------------
__device__ __align__(256) float g_qkv[(size_t)TB * TT * 3 * TC];       // [4096][3072] fp32
__device__ __align__(256) __nv_bfloat16 g_xh[(size_t)TB * TT * TC];    // x hi
__device__ __align__(256) __nv_bfloat16 g_xl[(size_t)TB * TT * TC];    // x lo
__device__ __align__(256) __nv_bfloat16 g_wqh[(size_t)TC * 3 * TC];
__device__ __align__(256) __nv_bfloat16 g_wql[(size_t)TC * 3 * TC];
__device__ __align__(256) __nv_bfloat16 g_woh[(size_t)TC * TC];
__device__ __align__(256) __nv_bfloat16 g_wol[(size_t)TC * TC];
__device__ __align__(256) __nv_bfloat16 g_ah[(size_t)TB * TT * TC];    // attn out hi
__device__ __align__(256) __nv_bfloat16 g_al[(size_t)TB * TT * TC];    // attn out lo

// ---------------------------------------------------------------------------
// Split fp32 -> (bf16 hi, bf16 lo) planes. n divisible by 4.
// ---------------------------------------------------------------------------
__global__ void split_kernel(const float* __restrict__ in,
                             __nv_bfloat16* __restrict__ hi,
                             __nv_bfloat16* __restrict__ lo, int n)
{
    int i = (blockIdx.x * blockDim.x + threadIdx.x) * 4;
    if (i >= n) return;
    float4 v = *(const float4*)(in + i);
    __nv_bfloat16 h0 = __float2bfloat16(v.x);
    __nv_bfloat16 h1 = __float2bfloat16(v.y);
    __nv_bfloat16 h2 = __float2bfloat16(v.z);
    __nv_bfloat16 h3 = __float2bfloat16(v.w);
    __nv_bfloat16 l0 = __float2bfloat16(v.x - __bfloat162float(h0));
    __nv_bfloat16 l1 = __float2bfloat16(v.y - __bfloat162float(h1));
    __nv_bfloat16 l2 = __float2bfloat16(v.z - __bfloat162float(h2));
    __nv_bfloat16 l3 = __float2bfloat16(v.w - __bfloat162float(h3));
    __nv_bfloat162* hp = (__nv_bfloat162*)(hi + i);
    __nv_bfloat162* lp = (__nv_bfloat162*)(lo + i);
    hp[0] = __nv_bfloat162{h0, h1}; hp[1] = __nv_bfloat162{h2, h3};
    lp[0] = __nv_bfloat162{l0, l1}; lp[1] = __nv_bfloat162{l2, l3};
}

// ---------------------------------------------------------------------------
// Split-bf16 GEMM: C[M,N] (fp32) = (Ah+Al)[M,K] @ (Bh+Bl)[K,N]
// acc = Ah*Bh + Ah*Bl + Al*Bh (lo*lo dropped, ~u^2 error).
// BM=BN=128, BK=32, 256 threads (8 warps: 2(M) x 4(N), warp tile 64x32).
// cp.async double buffered; ldmatrix with XOR swizzle.
// Requires M%128==0, N%128==0, K%32==0.
// ---------------------------------------------------------------------------
#define CP_ASYNC16(dst, src) \
    asm volatile("cp.async.cg.shared.global [%0], [%1], 16;\n" :: "r"(dst), "l"(src))
#define CP_COMMIT() asm volatile("cp.async.commit_group;\n" ::)
#define CP_WAIT1()  asm volatile("cp.async.wait_group 1;\n" ::)
#define CP_WAIT0()  asm volatile("cp.async.wait_group 0;\n" ::)

// smem stage layout (bytes): [0,8K) Ah, [8K,16K) Al, [16K,24K) Bh, [24K,32K) Bl
// A tile: [128 rows][32 bf16] = 64B rows, 4 x 16B chunks, swizzle ch^(row&3)
// B tile: [32 rows][128 bf16] = 256B rows, 16 x 16B chunks, swizzle ch^(row&7)
__device__ __forceinline__ void gemm_load_stage(
    uint32_t sb, int tid, int row0, int col0, int k0, int K, int N,
    const __nv_bfloat16* __restrict__ Ah, const __nv_bfloat16* __restrict__ Al,
    const __nv_bfloat16* __restrict__ Bh, const __nv_bfloat16* __restrict__ Bl)
{
    #pragma unroll
    for (int i = 0; i < 2; i++) {
        int idx = tid + i * 256;
        // A chunks
        int ra = idx >> 2, ca = idx & 3;
        uint32_t offa = ra * 64 + ((ca ^ (ra & 3)) << 4);
        size_t ga = (size_t)(row0 + ra) * K + k0 + ca * 8;
        CP_ASYNC16(sb + offa,        Ah + ga);
        CP_ASYNC16(sb + 8192 + offa, Al + ga);
        // B chunks
        int rb = idx >> 4, cb = idx & 15;
        uint32_t offb = rb * 256 + ((cb ^ (rb & 7)) << 4);
        size_t gb = (size_t)(k0 + rb) * N + col0 + cb * 8;
        CP_ASYNC16(sb + 16384 + offb, Bh + gb);
        CP_ASYNC16(sb + 24576 + offb, Bl + gb);
    }
    CP_COMMIT();
}

extern __shared__ char smem_raw[];

__global__ __launch_bounds__(256) void gemm_split_kernel(
    const __nv_bfloat16* __restrict__ Ah, const __nv_bfloat16* __restrict__ Al,
    const __nv_bfloat16* __restrict__ Bh, const __nv_bfloat16* __restrict__ Bl,
    float* __restrict__ C, int M, int N, int K)
{
    const int tid = threadIdx.x;
    const int warp = tid >> 5, lane = tid & 31;
    const int warpM = warp >> 2, warpN = warp & 3;   // 2 x 4
    const int row0 = blockIdx.y * 128, col0 = blockIdx.x * 128;
    const uint32_t smem_base = (uint32_t)__cvta_generic_to_shared(smem_raw);

    float acc[4][4][4];
    #pragma unroll
    for (int m = 0; m < 4; m++)
        #pragma unroll
        for (int n = 0; n < 4; n++)
            #pragma unroll
            for (int r = 0; r < 4; r++) acc[m][n][r] = 0.f;

    const int KT = K / 32;
    gemm_load_stage(smem_base,         tid, row0, col0, 0,  K, N, Ah, Al, Bh, Bl);
    gemm_load_stage(smem_base + 32768, tid, row0, col0, 32, K, N, Ah, Al, Bh, Bl);

    for (int kt = 0; kt < KT; kt++) {
        if (kt + 1 < KT) { CP_WAIT1(); } else { CP_WAIT0(); }
        __syncthreads();
        const uint32_t sb = smem_base + (kt & 1) * 32768;

        #pragma unroll
        for (int ks = 0; ks < 2; ks++) {
            // B fragments: [plane][n][2]
            uint32_t bfr[2][4][2];
            const int rB = ks * 16 + (lane & 15);
            #pragma unroll
            for (int p = 0; p < 2; p++) {
                #pragma unroll
                for (int n = 0; n < 4; n++) {
                    const int chunk = warpN * 4 + n;
                    uint32_t addr = sb + 16384 + p * 8192 + rB * 256
                                  + ((chunk ^ (rB & 7)) << 4);
                    asm volatile(
                        "ldmatrix.sync.aligned.m8n8.x2.trans.shared.b16 {%0,%1}, [%2];"
                        : "=r"(bfr[p][n][0]), "=r"(bfr[p][n][1]) : "r"(addr));
                }
            }
            #pragma unroll
            for (int m = 0; m < 4; m++) {
                uint32_t afr[2][4];
                const int rA = warpM * 64 + m * 16 + (lane & 15);
                const int chA = ks * 2 + (lane >> 4);
                #pragma unroll
                for (int p = 0; p < 2; p++) {
                    uint32_t addr = sb + p * 8192 + rA * 64
                                  + ((chA ^ (rA & 3)) << 4);
                    asm volatile(
                        "ldmatrix.sync.aligned.m8n8.x4.shared.b16 {%0,%1,%2,%3}, [%4];"
                        : "=r"(afr[p][0]), "=r"(afr[p][1]),
                          "=r"(afr[p][2]), "=r"(afr[p][3]) : "r"(addr));
                }
                #pragma unroll
                for (int n = 0; n < 4; n++) {
                    #define MMA(A, B)                                            \
                        asm volatile(                                            \
                            "mma.sync.aligned.m16n8k16.row.col.f32.bf16.bf16.f32 " \
                            "{%0,%1,%2,%3}, {%4,%5,%6,%7}, {%8,%9}, {%0,%1,%2,%3};" \
                            : "+f"(acc[m][n][0]), "+f"(acc[m][n][1]),            \
                              "+f"(acc[m][n][2]), "+f"(acc[m][n][3])             \
                            : "r"(A[0]), "r"(A[1]), "r"(A[2]), "r"(A[3]),        \
                              "r"(B[0]), "r"(B[1]))
                    MMA(afr[0], bfr[0][n]);   // hi * hi
                    MMA(afr[0], bfr[1][n]);   // hi * lo
                    MMA(afr[1], bfr[0][n]);   // lo * hi
                    #undef MMA
                }
            }
        }
        __syncthreads();
        if (kt + 2 < KT)
            gemm_load_stage(smem_base + (kt & 1) * 32768, tid, row0, col0,
                            (kt + 2) * 32, K, N, Ah, Al, Bh, Bl);
    }

    // Epilogue
    #pragma unroll
    for (int m = 0; m < 4; m++) {
        #pragma unroll
        for (int n = 0; n < 4; n++) {
            const int r = row0 + warpM * 64 + m * 16 + (lane >> 2);
            const int c = col0 + warpN * 32 + n * 8 + (lane & 3) * 2;
            *(float2*)(C + (size_t)r * N + c) =
                make_float2(acc[m][n][0], acc[m][n][1]);
            *(float2*)(C + (size_t)(r + 8) * N + c) =
                make_float2(acc[m][n][2], acc[m][n][3]);
        }
    }
}

// ---------------------------------------------------------------------------
// Flash attention (causal), fp32, heavy-block-first scheduling.
// grid = (T/128, B*H), block = 128. One thread = one query row.
// Output written as bf16 hi/lo planes for the split-bf16 out-projection.
// ---------------------------------------------------------------------------
__global__ __launch_bounds__(128) void attn_kernel(
    const float* __restrict__ qkv,
    __nv_bfloat16* __restrict__ outh, __nv_bfloat16* __restrict__ outl)
{
    __shared__ float Ks[64 * TD];
    __shared__ float Vs[64 * TD];

    const int b = blockIdx.y >> 4;
    const int h = blockIdx.y & 15;
    const int qb = gridDim.x - 1 - blockIdx.x;      // heavy blocks first
    const int r = qb * 128 + threadIdx.x;           // query row
    const size_t rowstride = 3 * TC;

    float q[TD];
    {
        const float* qp = qkv + ((size_t)b * TT + r) * rowstride + h * TD;
        #pragma unroll
        for (int d = 0; d < TD; d += 4) {
            float4 v4 = *(const float4*)(qp + d);
            q[d] = v4.x; q[d + 1] = v4.y; q[d + 2] = v4.z; q[d + 3] = v4.w;
        }
    }

    float o[TD];
    #pragma unroll
    for (int d = 0; d < TD; d++) o[d] = 0.f;
    float m = -3.0e38f, l = 0.f;

    const int kend = qb * 128 + 128;

    #pragma unroll 1
    for (int j0 = 0; j0 < kend; j0 += 64) {
        __syncthreads();
        #pragma unroll
        for (int i = 0; i < 8; i++) {
            int idx = threadIdx.x + i * 128;
            int row = idx >> 4;
            int cv  = (idx & 15) << 2;
            const float* kp = qkv + ((size_t)b * TT + j0 + row) * rowstride
                              + TC + h * TD + cv;
            *(float4*)(Ks + row * TD + cv) = *(const float4*)kp;
            *(float4*)(Vs + row * TD + cv) = *(const float4*)(kp + TC);
        }
        __syncthreads();

        #pragma unroll 1
        for (int jc = 0; jc < 4; jc++) {
            float s[16];
            float mt = m;
            #pragma unroll
            for (int jj = 0; jj < 16; jj++) {
                const int j = jc * 16 + jj;
                float acc = 0.f;
                const float* kk = Ks + j * TD;
                #pragma unroll
                for (int d = 0; d < TD; d += 4) {
                    float4 k4 = *(const float4*)(kk + d);
                    acc = fmaf(q[d],     k4.x, acc);
                    acc = fmaf(q[d + 1], k4.y, acc);
                    acc = fmaf(q[d + 2], k4.z, acc);
                    acc = fmaf(q[d + 3], k4.w, acc);
                }
                acc *= 0.125f;
                if (j0 + j > r) acc = -1e30f;
                s[jj] = acc;
                mt = fmaxf(mt, acc);
            }
            float resc = __expf(m - mt);
            m = mt;
            l *= resc;
            #pragma unroll
            for (int d = 0; d < TD; d++) o[d] *= resc;
            #pragma unroll
            for (int jj = 0; jj < 16; jj++) {
                float p = __expf(s[jj] - m);
                l += p;
                const float* vv = Vs + (jc * 16 + jj) * TD;
                #pragma unroll
                for (int d = 0; d < TD; d += 4) {
                    float4 v4 = *(const float4*)(vv + d);
                    o[d]     = fmaf(p, v4.x, o[d]);
                    o[d + 1] = fmaf(p, v4.y, o[d + 1]);
                    o[d + 2] = fmaf(p, v4.z, o[d + 2]);
                    o[d + 3] = fmaf(p, v4.w, o[d + 3]);
                }
            }
        }
    }

    const float inv = 1.f / l;
    const size_t base = ((size_t)b * TT + r) * TC + h * TD;
    #pragma unroll
    for (int d = 0; d < TD; d += 2) {
        float v0 = o[d] * inv, v1 = o[d + 1] * inv;
        __nv_bfloat16 h0 = __float2bfloat16(v0);
        __nv_bfloat16 h1 = __float2bfloat16(v1);
        __nv_bfloat16 l0 = __float2bfloat16(v0 - __bfloat162float(h0));
        __nv_bfloat16 l1 = __float2bfloat16(v1 - __bfloat162float(h1));
        *(__nv_bfloat162*)(outh + base + d) = __nv_bfloat162{h0, h1};
        *(__nv_bfloat162*)(outl + base + d) = __nv_bfloat162{l0, l1};
    }
}

// ---------------------------------------------------------------------------
extern "C" void kernel_launch(void* const* d_in, const int* in_sizes, int n_in,
                              void* d_out, int out_size)
{
    const float* x    = (const float*)d_in[0];   // [B,T,C]
    const float* Wqkv = (const float*)d_in[1];   // [C,3C]
    const float* Wout = (const float*)d_in[2];   // [C,C]
    float* out = (float*)d_out;                  // [B,T,C]

    float* qkv_ptr;
    __nv_bfloat16 *xh, *xl, *wqh, *wql, *woh, *wol, *ah, *al;
    cudaGetSymbolAddress((void**)&qkv_ptr, g_qkv);
    cudaGetSymbolAddress((void**)&xh, g_xh);   cudaGetSymbolAddress((void**)&xl, g_xl);
    cudaGetSymbolAddress((void**)&wqh, g_wqh); cudaGetSymbolAddress((void**)&wql, g_wql);
    cudaGetSymbolAddress((void**)&woh, g_woh); cudaGetSymbolAddress((void**)&wol, g_wol);
    cudaGetSymbolAddress((void**)&ah, g_ah);   cudaGetSymbolAddress((void**)&al, g_al);

    cudaFuncSetAttribute(gemm_split_kernel,
                         cudaFuncAttributeMaxDynamicSharedMemorySize, 65536);

    const int M = TB * TT;            // 4096
    const int nx  = M * TC;           // 4.19M
    const int nwq = TC * 3 * TC;      // 3.15M
    const int nwo = TC * TC;          // 1.05M

    split_kernel<<<nx  / 1024, 256>>>(x, xh, xl, nx);
    split_kernel<<<nwq / 1024, 256>>>(Wqkv, wqh, wql, nwq);
    split_kernel<<<nwo / 1024, 256>>>(Wout, woh, wol, nwo);

    // 1) QKV projection: [4096,1024] @ [1024,3072] -> fp32
    gemm_split_kernel<<<dim3((3 * TC) / 128, M / 128), 256, 65536>>>(
        xh, xl, wqh, wql, qkv_ptr, M, 3 * TC, TC);

    // 2) Causal flash attention -> bf16 hi/lo planes
    attn_kernel<<<dim3(TT / 128, TB * TH), 128>>>(qkv_ptr, ah, al);

    // 3) Output projection: [4096,1024] @ [1024,1024] -> fp32 out
    gemm_split_kernel<<<dim3(TC / 128, M / 128), 256, 65536>>>(
        ah, al, woh, wol, out, M, TC, TC);
}

// round 3
// speedup vs baseline: 3.3854x; 2.5023x over previous
#include <cuda_runtime.h>
#include <cuda_bf16.h>
#include <cstdint>
#include <cstddef>

// Problem constants
#define TB 2
#define TT 2048
#define TC 1024
#define TH 16
#define TD 64

// ---------------------------------------------------------------------------
// Scratch (__device__ globals; allocation-free rule)
// ---------------------------------------------------------------------------
__device__ __align__(256) __nv_bfloat16 g_qkvh[(size_t)TB * TT * 3 * TC];
__device__ __align__(256) __nv_bfloat16 g_qkvl[(size_t)TB * TT * 3 * TC];
__device__ __align__(256) __nv_bfloat16 g_xh[(size_t)TB * TT * TC];
__device__ __align__(256) __nv_bfloat16 g_xl[(size_t)TB * TT * TC];
__device__ __align__(256) __nv_bfloat16 g_wqh[(size_t)TC * 3 * TC];
__device__ __align__(256) __nv_bfloat16 g_wql[(size_t)TC * 3 * TC];
__device__ __align__(256) __nv_bfloat16 g_woh[(size_t)TC * TC];
__device__ __align__(256) __nv_bfloat16 g_wol[(size_t)TC * TC];
__device__ __align__(256) __nv_bfloat16 g_ah[(size_t)TB * TT * TC];
__device__ __align__(256) __nv_bfloat16 g_al[(size_t)TB * TT * TC];

// ---------------------------------------------------------------------------
__device__ __forceinline__ void split_pack(float x, float y,
                                           uint32_t& hi, uint32_t& lo)
{
    __nv_bfloat162 h = __float22bfloat162_rn(make_float2(x, y));
    float hx = __bfloat162float(h.x), hy = __bfloat162float(h.y);
    __nv_bfloat162 l = __float22bfloat162_rn(make_float2(x - hx, y - hy));
    hi = *(uint32_t*)&h;
    lo = *(uint32_t*)&l;
}

__device__ __forceinline__ void mma_bf16(float* d, const uint32_t* a,
                                         const uint32_t* b)
{
    asm volatile(
        "mma.sync.aligned.m16n8k16.row.col.f32.bf16.bf16.f32 "
        "{%0,%1,%2,%3}, {%4,%5,%6,%7}, {%8,%9}, {%0,%1,%2,%3};"
        : "+f"(d[0]), "+f"(d[1]), "+f"(d[2]), "+f"(d[3])
        : "r"(a[0]), "r"(a[1]), "r"(a[2]), "r"(a[3]), "r"(b[0]), "r"(b[1]));
}

// ---------------------------------------------------------------------------
// Split fp32 -> (bf16 hi, bf16 lo) planes. n divisible by 4.
// ---------------------------------------------------------------------------
__global__ void split_kernel(const float* __restrict__ in,
                             __nv_bfloat16* __restrict__ hi,
                             __nv_bfloat16* __restrict__ lo, int n)
{
    int i = (blockIdx.x * blockDim.x + threadIdx.x) * 4;
    if (i >= n) return;
    float4 v = *(const float4*)(in + i);
    uint32_t h0, l0, h1, l1;
    split_pack(v.x, v.y, h0, l0);
    split_pack(v.z, v.w, h1, l1);
    uint32_t* hp = (uint32_t*)(hi + i);
    uint32_t* lp = (uint32_t*)(lo + i);
    hp[0] = h0; hp[1] = h1;
    lp[0] = l0; lp[1] = l1;
}

// ---------------------------------------------------------------------------
// Split-bf16 GEMM (as round 2) with selectable epilogue:
// mode 0: fp32 C.  mode 1: bf16 hi/lo planes Ch/Cl.
// ---------------------------------------------------------------------------
#define CP_ASYNC16(dst, src) \
    asm volatile("cp.async.cg.shared.global [%0], [%1], 16;\n" :: "r"(dst), "l"(src))
#define CP_COMMIT() asm volatile("cp.async.commit_group;\n" ::)
#define CP_WAIT1()  asm volatile("cp.async.wait_group 1;\n" ::)
#define CP_WAIT0()  asm volatile("cp.async.wait_group 0;\n" ::)

__device__ __forceinline__ void gemm_load_stage(
    uint32_t sb, int tid, int row0, int col0, int k0, int K, int N,
    const __nv_bfloat16* __restrict__ Ah, const __nv_bfloat16* __restrict__ Al,
    const __nv_bfloat16* __restrict__ Bh, const __nv_bfloat16* __restrict__ Bl)
{
    #pragma unroll
    for (int i = 0; i < 2; i++) {
        int idx = tid + i * 256;
        int ra = idx >> 2, ca = idx & 3;
        uint32_t offa = ra * 64 + ((ca ^ (ra & 3)) << 4);
        size_t ga = (size_t)(row0 + ra) * K + k0 + ca * 8;
        CP_ASYNC16(sb + offa,        Ah + ga);
        CP_ASYNC16(sb + 8192 + offa, Al + ga);
        int rb = idx >> 4, cb = idx & 15;
        uint32_t offb = rb * 256 + ((cb ^ (rb & 7)) << 4);
        size_t gb = (size_t)(k0 + rb) * N + col0 + cb * 8;
        CP_ASYNC16(sb + 16384 + offb, Bh + gb);
        CP_ASYNC16(sb + 24576 + offb, Bl + gb);
    }
    CP_COMMIT();
}

extern __shared__ char smem_raw[];

__global__ __launch_bounds__(256) void gemm_split_kernel(
    const __nv_bfloat16* __restrict__ Ah, const __nv_bfloat16* __restrict__ Al,
    const __nv_bfloat16* __restrict__ Bh, const __nv_bfloat16* __restrict__ Bl,
    float* __restrict__ C,
    __nv_bfloat16* __restrict__ Ch, __nv_bfloat16* __restrict__ Cl,
    int M, int N, int K, int mode)
{
    const int tid = threadIdx.x;
    const int warp = tid >> 5, lane = tid & 31;
    const int warpM = warp >> 2, warpN = warp & 3;
    const int row0 = blockIdx.y * 128, col0 = blockIdx.x * 128;
    const uint32_t smem_base = (uint32_t)__cvta_generic_to_shared(smem_raw);

    float acc[4][4][4];
    #pragma unroll
    for (int m = 0; m < 4; m++)
        #pragma unroll
        for (int n = 0; n < 4; n++)
            #pragma unroll
            for (int r = 0; r < 4; r++) acc[m][n][r] = 0.f;

    const int KT = K / 32;
    gemm_load_stage(smem_base,         tid, row0, col0, 0,  K, N, Ah, Al, Bh, Bl);
    gemm_load_stage(smem_base + 32768, tid, row0, col0, 32, K, N, Ah, Al, Bh, Bl);

    for (int kt = 0; kt < KT; kt++) {
        if (kt + 1 < KT) { CP_WAIT1(); } else { CP_WAIT0(); }
        __syncthreads();
        const uint32_t sb = smem_base + (kt & 1) * 32768;

        #pragma unroll
        for (int ks = 0; ks < 2; ks++) {
            uint32_t bfr[2][4][2];
            const int rB = ks * 16 + (lane & 15);
            #pragma unroll
            for (int p = 0; p < 2; p++) {
                #pragma unroll
                for (int n = 0; n < 4; n++) {
                    const int chunk = warpN * 4 + n;
                    uint32_t addr = sb + 16384 + p * 8192 + rB * 256
                                  + ((chunk ^ (rB & 7)) << 4);
                    asm volatile(
                        "ldmatrix.sync.aligned.m8n8.x2.trans.shared.b16 {%0,%1}, [%2];"
                        : "=r"(bfr[p][n][0]), "=r"(bfr[p][n][1]) : "r"(addr));
                }
            }
            #pragma unroll
            for (int m = 0; m < 4; m++) {
                uint32_t afr[2][4];
                const int rA = warpM * 64 + m * 16 + (lane & 15);
                const int chA = ks * 2 + (lane >> 4);
                #pragma unroll
                for (int p = 0; p < 2; p++) {
                    uint32_t addr = sb + p * 8192 + rA * 64
                                  + ((chA ^ (rA & 3)) << 4);
                    asm volatile(
                        "ldmatrix.sync.aligned.m8n8.x4.shared.b16 {%0,%1,%2,%3}, [%4];"
                        : "=r"(afr[p][0]), "=r"(afr[p][1]),
                          "=r"(afr[p][2]), "=r"(afr[p][3]) : "r"(addr));
                }
                #pragma unroll
                for (int n = 0; n < 4; n++) {
                    mma_bf16(acc[m][n], afr[0], bfr[0][n]);
                    mma_bf16(acc[m][n], afr[0], bfr[1][n]);
                    mma_bf16(acc[m][n], afr[1], bfr[0][n]);
                }
            }
        }
        __syncthreads();
        if (kt + 2 < KT)
            gemm_load_stage(smem_base + (kt & 1) * 32768, tid, row0, col0,
                            (kt + 2) * 32, K, N, Ah, Al, Bh, Bl);
    }

    #pragma unroll
    for (int m = 0; m < 4; m++) {
        #pragma unroll
        for (int n = 0; n < 4; n++) {
            const int r = row0 + warpM * 64 + m * 16 + (lane >> 2);
            const int c = col0 + warpN * 32 + n * 8 + (lane & 3) * 2;
            if (mode == 0) {
                *(float2*)(C + (size_t)r * N + c) =
                    make_float2(acc[m][n][0], acc[m][n][1]);
                *(float2*)(C + (size_t)(r + 8) * N + c) =
                    make_float2(acc[m][n][2], acc[m][n][3]);
            } else {
                uint32_t h0, l0, h1, l1;
                split_pack(acc[m][n][0], acc[m][n][1], h0, l0);
                split_pack(acc[m][n][2], acc[m][n][3], h1, l1);
                *(uint32_t*)(Ch + (size_t)r * N + c)       = h0;
                *(uint32_t*)(Cl + (size_t)r * N + c)       = l0;
                *(uint32_t*)(Ch + (size_t)(r + 8) * N + c) = h1;
                *(uint32_t*)(Cl + (size_t)(r + 8) * N + c) = l1;
            }
        }
    }
}

// ---------------------------------------------------------------------------
// Tensor-core flash attention (causal), bf16 hi/lo split.
// grid = (16, B*H), block = 128 (4 warps). CTA = 128 q rows, warp = 32 rows.
// Key tiles of 64, cp.async double-buffered. O frag & softmax fp32 in regs.
//
// smem: Qh[128][64] @0, Ql @16384, stages @32768 + s*32768:
//       {Kh @0, Kl @8192, Vh @16384, Vl @24576}, rows 128B, swizzle ch^(r&7).
// ---------------------------------------------------------------------------
__device__ __forceinline__ void attn_load_kv(
    uint32_t stage, int tid, int b, int h0, int j0,
    const __nv_bfloat16* __restrict__ qkvh,
    const __nv_bfloat16* __restrict__ qkvl)
{
    #pragma unroll
    for (int i = 0; i < 16; i++) {
        int idx = tid + i * 128;          // 0..2047
        int field = idx >> 9;             // 0:Kh 1:Kl 2:Vh 3:Vl
        int rem = idx & 511;
        int r = rem >> 3, ch = rem & 7;
        const __nv_bfloat16* src = (field & 1) ? qkvl : qkvh;
        int col = ((field >> 1) ? 2048 : 1024) + h0 * 64 + ch * 8;
        const __nv_bfloat16* gp = src + ((size_t)(b * TT + j0 + r)) * 3072 + col;
        uint32_t off = stage + field * 8192 + r * 128 + ((ch ^ (r & 7)) << 4);
        CP_ASYNC16(off, gp);
    }
}

__global__ __launch_bounds__(128) void attn_mma_kernel(
    const __nv_bfloat16* __restrict__ qkvh,
    const __nv_bfloat16* __restrict__ qkvl,
    __nv_bfloat16* __restrict__ outh, __nv_bfloat16* __restrict__ outl)
{
    const int tid = threadIdx.x;
    const int warp = tid >> 5, lane = tid & 31;
    const int b = blockIdx.y >> 4;
    const int h0 = blockIdx.y & 15;
    const int qb = gridDim.x - 1 - blockIdx.x;     // heavy blocks first
    const int qbase = qb * 128;
    const uint32_t smem_base = (uint32_t)__cvta_generic_to_shared(smem_raw);

    // --- load Q tile (both planes) ---
    #pragma unroll
    for (int i = 0; i < 16; i++) {
        int idx = tid + i * 128;          // 0..2047
        int plane = idx >> 10;
        int rem = idx & 1023;
        int r = rem >> 3, ch = rem & 7;
        const __nv_bfloat16* src = plane ? qkvl : qkvh;
        const __nv_bfloat16* gp =
            src + ((size_t)(b * TT + qbase + r)) * 3072 + h0 * 64 + ch * 8;
        uint32_t off = smem_base + plane * 16384 + r * 128 + ((ch ^ (r & 7)) << 4);
        CP_ASYNC16(off, gp);
    }
    const int nkb = 2 * (qb + 1);
    attn_load_kv(smem_base + 32768, tid, b, h0, 0, qkvh, qkvl);
    CP_COMMIT();
    if (nkb > 1) attn_load_kv(smem_base + 65536, tid, b, h0, 64, qkvh, qkvl);
    CP_COMMIT();

    uint32_t qf[2][2][4][4];      // [plane][mtile][ktile][reg]
    float o[2][8][4];
    float mrow[2][2], lrow[2][2];
    #pragma unroll
    for (int m = 0; m < 2; m++) {
        #pragma unroll
        for (int n = 0; n < 8; n++)
            #pragma unroll
            for (int c = 0; c < 4; c++) o[m][n][c] = 0.f;
        mrow[m][0] = mrow[m][1] = -3.0e38f;
        lrow[m][0] = lrow[m][1] = 0.f;
    }

    const int rbase = qbase + warp * 32;

    for (int kb = 0; kb < nkb; kb++) {
        if (kb + 1 < nkb) { CP_WAIT1(); } else { CP_WAIT0(); }
        __syncthreads();

        if (kb == 0) {
            // Q fragments (once)
            #pragma unroll
            for (int p = 0; p < 2; p++)
                #pragma unroll
                for (int m = 0; m < 2; m++) {
                    const int rA = warp * 32 + m * 16 + (lane & 15);
                    #pragma unroll
                    for (int kt = 0; kt < 4; kt++) {
                        const int ch = kt * 2 + (lane >> 4);
                        uint32_t addr = smem_base + p * 16384 + rA * 128
                                      + ((ch ^ (rA & 7)) << 4);
                        asm volatile(
                            "ldmatrix.sync.aligned.m8n8.x4.shared.b16 "
                            "{%0,%1,%2,%3}, [%4];"
                            : "=r"(qf[p][m][kt][0]), "=r"(qf[p][m][kt][1]),
                              "=r"(qf[p][m][kt][2]), "=r"(qf[p][m][kt][3])
                            : "r"(addr));
                    }
                }
        }

        const uint32_t sk = smem_base + 32768 + (kb & 1) * 32768;
        const int j0 = kb * 64;

        // ---- S = Q @ K^T (split 3-term) ----
        float acc[2][8][4];
        #pragma unroll
        for (int m = 0; m < 2; m++)
            #pragma unroll
            for (int n = 0; n < 8; n++)
                #pragma unroll
                for (int c = 0; c < 4; c++) acc[m][n][c] = 0.f;

        const int l16 = lane & 15;
        #pragma unroll
        for (int n = 0; n < 8; n++) {
            #pragma unroll
            for (int kt = 0; kt < 4; kt++) {
                uint32_t kbf[2][2];
                const int rK = n * 8 + (l16 & 7);
                const int ch = kt * 2 + (l16 >> 3);
                #pragma unroll
                for (int p = 0; p < 2; p++) {
                    uint32_t addr = sk + p * 8192 + rK * 128
                                  + ((ch ^ (rK & 7)) << 4);
                    asm volatile(
                        "ldmatrix.sync.aligned.m8n8.x2.shared.b16 {%0,%1}, [%2];"
                        : "=r"(kbf[p][0]), "=r"(kbf[p][1]) : "r"(addr));
                }
                #pragma unroll
                for (int m = 0; m < 2; m++) {
                    mma_bf16(acc[m][n], qf[0][m][kt], kbf[0]);   // hi*hi
                    mma_bf16(acc[m][n], qf[0][m][kt], kbf[1]);   // hi*lo
                    mma_bf16(acc[m][n], qf[1][m][kt], kbf[0]);   // lo*hi
                }
            }
        }

        // ---- scale + causal mask ----
        const bool diag = (j0 >= qbase);
        #pragma unroll
        for (int m = 0; m < 2; m++)
            #pragma unroll
            for (int n = 0; n < 8; n++)
                #pragma unroll
                for (int c = 0; c < 4; c++) {
                    float v = acc[m][n][c] * 0.125f;
                    if (diag) {
                        int col = j0 + n * 8 + ((lane & 3) << 1) + (c & 1);
                        int row = rbase + m * 16 + (lane >> 2) + ((c >> 1) << 3);
                        if (col > row) v = -1e30f;
                    }
                    acc[m][n][c] = v;
                }

        // ---- online softmax; P replaces acc ----
        #pragma unroll
        for (int m = 0; m < 2; m++) {
            #pragma unroll
            for (int h = 0; h < 2; h++) {
                float mt = mrow[m][h];
                #pragma unroll
                for (int n = 0; n < 8; n++)
                    mt = fmaxf(mt, fmaxf(acc[m][n][2 * h], acc[m][n][2 * h + 1]));
                mt = fmaxf(mt, __shfl_xor_sync(0xffffffffu, mt, 1));
                mt = fmaxf(mt, __shfl_xor_sync(0xffffffffu, mt, 2));
                float rs = __expf(mrow[m][h] - mt);
                mrow[m][h] = mt;
                float lsum = 0.f;
                #pragma unroll
                for (int n = 0; n < 8; n++) {
                    float p0 = __expf(acc[m][n][2 * h]     - mt);
                    float p1 = __expf(acc[m][n][2 * h + 1] - mt);
                    acc[m][n][2 * h]     = p0;
                    acc[m][n][2 * h + 1] = p1;
                    lsum += p0 + p1;
                    o[m][n][2 * h]     *= rs;
                    o[m][n][2 * h + 1] *= rs;
                }
                lrow[m][h] = lrow[m][h] * rs + lsum;
            }
        }

        // ---- O += P @ V (split 3-term) ----
        #pragma unroll
        for (int kt = 0; kt < 4; kt++) {
            uint32_t pah[2][4], pal[2][4];
            #pragma unroll
            for (int m = 0; m < 2; m++) {
                split_pack(acc[m][2 * kt][0],     acc[m][2 * kt][1],     pah[m][0], pal[m][0]);
                split_pack(acc[m][2 * kt][2],     acc[m][2 * kt][3],     pah[m][1], pal[m][1]);
                split_pack(acc[m][2 * kt + 1][0], acc[m][2 * kt + 1][1], pah[m][2], pal[m][2]);
                split_pack(acc[m][2 * kt + 1][2], acc[m][2 * kt + 1][3], pah[m][3], pal[m][3]);
            }
            #pragma unroll
            for (int n = 0; n < 8; n++) {
                uint32_t vbf[2][2];
                const int rV = kt * 16 + l16;
                #pragma unroll
                for (int p = 0; p < 2; p++) {
                    uint32_t addr = sk + 16384 + p * 8192 + rV * 128
                                  + ((n ^ (rV & 7)) << 4);
                    asm volatile(
                        "ldmatrix.sync.aligned.m8n8.x2.trans.shared.b16 {%0,%1}, [%2];"
                        : "=r"(vbf[p][0]), "=r"(vbf[p][1]) : "r"(addr));
                }
                #pragma unroll
                for (int m = 0; m < 2; m++) {
                    mma_bf16(o[m][n], pah[m], vbf[0]);   // ph*vh
                    mma_bf16(o[m][n], pal[m], vbf[0]);   // pl*vh
                    mma_bf16(o[m][n], pah[m], vbf[1]);   // ph*vl
                }
            }
        }

        __syncthreads();
        if (kb + 2 < nkb) {
            attn_load_kv(smem_base + 32768 + (kb & 1) * 32768, tid, b, h0,
                         (kb + 2) * 64, qkvh, qkvl);
            CP_COMMIT();
        }
    }

    // ---- normalize + write bf16 hi/lo ----
    float inv[2][2];
    #pragma unroll
    for (int m = 0; m < 2; m++)
        #pragma unroll
        for (int h = 0; h < 2; h++) {
            float lt = lrow[m][h];
            lt += __shfl_xor_sync(0xffffffffu, lt, 1);
            lt += __shfl_xor_sync(0xffffffffu, lt, 2);
            inv[m][h] = 1.f / lt;
        }

    #pragma unroll
    for (int m = 0; m < 2; m++) {
        const int r0 = rbase + m * 16 + (lane >> 2);
        #pragma unroll
        for (int n = 0; n < 8; n++) {
            const int cd = h0 * 64 + n * 8 + ((lane & 3) << 1);
            uint32_t h_, l_;
            split_pack(o[m][n][0] * inv[m][0], o[m][n][1] * inv[m][0], h_, l_);
            size_t base0 = (size_t)(b * TT + r0) * 1024 + cd;
            *(uint32_t*)(outh + base0) = h_;
            *(uint32_t*)(outl + base0) = l_;
            split_pack(o[m][n][2] * inv[m][1], o[m][n][3] * inv[m][1], h_, l_);
            size_t base1 = (size_t)(b * TT + r0 + 8) * 1024 + cd;
            *(uint32_t*)(outh + base1) = h_;
            *(uint32_t*)(outl + base1) = l_;
        }
    }
}

// ---------------------------------------------------------------------------
extern "C" void kernel_launch(void* const* d_in, const int* in_sizes, int n_in,
                              void* d_out, int out_size)
{
    const float* x    = (const float*)d_in[0];
    const float* Wqkv = (const float*)d_in[1];
    const float* Wout = (const float*)d_in[2];
    float* out = (float*)d_out;

    __nv_bfloat16 *qkvh, *qkvl, *xh, *xl, *wqh, *wql, *woh, *wol, *ah, *al;
    cudaGetSymbolAddress((void**)&qkvh, g_qkvh); cudaGetSymbolAddress((void**)&qkvl, g_qkvl);
    cudaGetSymbolAddress((void**)&xh, g_xh);     cudaGetSymbolAddress((void**)&xl, g_xl);
    cudaGetSymbolAddress((void**)&wqh, g_wqh);   cudaGetSymbolAddress((void**)&wql, g_wql);
    cudaGetSymbolAddress((void**)&woh, g_woh);   cudaGetSymbolAddress((void**)&wol, g_wol);
    cudaGetSymbolAddress((void**)&ah, g_ah);     cudaGetSymbolAddress((void**)&al, g_al);

    cudaFuncSetAttribute(gemm_split_kernel,
                         cudaFuncAttributeMaxDynamicSharedMemorySize, 65536);
    cudaFuncSetAttribute(attn_mma_kernel,
                         cudaFuncAttributeMaxDynamicSharedMemorySize, 98304);

    const int M = TB * TT;            // 4096
    const int nx  = M * TC;
    const int nwq = TC * 3 * TC;
    const int nwo = TC * TC;

    split_kernel<<<nx  / 1024, 256>>>(x, xh, xl, nx);
    split_kernel<<<nwq / 1024, 256>>>(Wqkv, wqh, wql, nwq);
    split_kernel<<<nwo / 1024, 256>>>(Wout, woh, wol, nwo);

    // 1) QKV projection -> bf16 hi/lo planes
    gemm_split_kernel<<<dim3((3 * TC) / 128, M / 128), 256, 65536>>>(
        xh, xl, wqh, wql, nullptr, qkvh, qkvl, M, 3 * TC, TC, 1);

    // 2) Tensor-core causal flash attention -> bf16 hi/lo planes
    attn_mma_kernel<<<dim3(TT / 128, TB * TH), 128, 98304>>>(qkvh, qkvl, ah, al);

    // 3) Output projection -> fp32 out
    gemm_split_kernel<<<dim3(TC / 128, M / 128), 256, 65536>>>(
        ah, al, woh, wol, out, nullptr, nullptr, M, TC, TC, 0);
}

// round 5
// speedup vs baseline: 3.3879x; 1.0007x over previous
#include <cuda_runtime.h>
#include <cuda_bf16.h>
#include <cstdint>
#include <cstddef>

// Problem constants
#define TB 2
#define TT 2048
#define TC 1024
#define TH 16
#define TD 64

// ---------------------------------------------------------------------------
// Scratch (__device__ globals; allocation-free rule)
// ---------------------------------------------------------------------------
__device__ __align__(256) __nv_bfloat16 g_qkvh[(size_t)TB * TT * 3 * TC];
__device__ __align__(256) __nv_bfloat16 g_qkvl[(size_t)TB * TT * 3 * TC];
__device__ __align__(256) __nv_bfloat16 g_xh[(size_t)TB * TT * TC];
__device__ __align__(256) __nv_bfloat16 g_xl[(size_t)TB * TT * TC];
__device__ __align__(256) __nv_bfloat16 g_wqh[(size_t)TC * 3 * TC];
__device__ __align__(256) __nv_bfloat16 g_wql[(size_t)TC * 3 * TC];
__device__ __align__(256) __nv_bfloat16 g_woh[(size_t)TC * TC];
__device__ __align__(256) __nv_bfloat16 g_wol[(size_t)TC * TC];
__device__ __align__(256) __nv_bfloat16 g_ah[(size_t)TB * TT * TC];
__device__ __align__(256) __nv_bfloat16 g_al[(size_t)TB * TT * TC];

// ---------------------------------------------------------------------------
__device__ __forceinline__ void split_pack(float x, float y,
                                           uint32_t& hi, uint32_t& lo)
{
    __nv_bfloat162 h = __float22bfloat162_rn(make_float2(x, y));
    float hx = __bfloat162float(h.x), hy = __bfloat162float(h.y);
    __nv_bfloat162 l = __float22bfloat162_rn(make_float2(x - hx, y - hy));
    hi = *(uint32_t*)&h;
    lo = *(uint32_t*)&l;
}

__device__ __forceinline__ void mma_bf16(float* d, const uint32_t* a,
                                         const uint32_t* b)
{
    asm volatile(
        "mma.sync.aligned.m16n8k16.row.col.f32.bf16.bf16.f32 "
        "{%0,%1,%2,%3}, {%4,%5,%6,%7}, {%8,%9}, {%0,%1,%2,%3};"
        : "+f"(d[0]), "+f"(d[1]), "+f"(d[2]), "+f"(d[3])
        : "r"(a[0]), "r"(a[1]), "r"(a[2]), "r"(a[3]), "r"(b[0]), "r"(b[1]));
}

// ---------------------------------------------------------------------------
// Split fp32 -> (bf16 hi, bf16 lo) planes. n divisible by 4.
// ---------------------------------------------------------------------------
__global__ void split_kernel(const float* __restrict__ in,
                             __nv_bfloat16* __restrict__ hi,
                             __nv_bfloat16* __restrict__ lo, int n)
{
    int i = (blockIdx.x * blockDim.x + threadIdx.x) * 4;
    if (i >= n) return;
    float4 v = *(const float4*)(in + i);
    uint32_t h0, l0, h1, l1;
    split_pack(v.x, v.y, h0, l0);
    split_pack(v.z, v.w, h1, l1);
    uint32_t* hp = (uint32_t*)(hi + i);
    uint32_t* lp = (uint32_t*)(lo + i);
    hp[0] = h0; hp[1] = h1;
    lp[0] = l0; lp[1] = l1;
}

// ---------------------------------------------------------------------------
// Split-bf16 GEMM: C[M,N] (fp32) = (Ah+Al)[M,K] @ (Bh+Bl)[K,N]
// acc = Ah*Bh + Ah*Bl + Al*Bh.  BM=BN=128, BK=32, 256 threads
// (8 warps: 2(M) x 4(N), warp tile 64x32).  3-stage cp.async pipeline.
// mode 0: fp32 C.  mode 1: bf16 hi/lo planes Ch/Cl.
// stage layout (32KB): Ah@0 Al@8K Bh@16K Bl@24K
// ---------------------------------------------------------------------------
#define CP_ASYNC16(dst, src) \
    asm volatile("cp.async.cg.shared.global [%0], [%1], 16;\n" :: "r"(dst), "l"(src))
#define CP_COMMIT() asm volatile("cp.async.commit_group;\n" ::)
#define CP_WAIT2()  asm volatile("cp.async.wait_group 2;\n" ::)
#define CP_WAIT1()  asm volatile("cp.async.wait_group 1;\n" ::)
#define CP_WAIT0()  asm volatile("cp.async.wait_group 0;\n" ::)

__device__ __forceinline__ void gemm_load_stage(
    uint32_t sb, int tid, int row0, int col0, int k0, int K, int N,
    const __nv_bfloat16* __restrict__ Ah, const __nv_bfloat16* __restrict__ Al,
    const __nv_bfloat16* __restrict__ Bh, const __nv_bfloat16* __restrict__ Bl)
{
    #pragma unroll
    for (int i = 0; i < 2; i++) {
        int idx = tid + i * 256;
        int ra = idx >> 2, ca = idx & 3;
        uint32_t offa = ra * 64 + ((ca ^ (ra & 3)) << 4);
        size_t ga = (size_t)(row0 + ra) * K + k0 + ca * 8;
        CP_ASYNC16(sb + offa,        Ah + ga);
        CP_ASYNC16(sb + 8192 + offa, Al + ga);
        int rb = idx >> 4, cb = idx & 15;
        uint32_t offb = rb * 256 + ((cb ^ (rb & 7)) << 4);
        size_t gb = (size_t)(k0 + rb) * N + col0 + cb * 8;
        CP_ASYNC16(sb + 16384 + offb, Bh + gb);
        CP_ASYNC16(sb + 24576 + offb, Bl + gb);
    }
    CP_COMMIT();
}

extern __shared__ __align__(1024) char smem_raw[];

__global__ __launch_bounds__(256) void gemm_split_kernel(
    const __nv_bfloat16* __restrict__ Ah, const __nv_bfloat16* __restrict__ Al,
    const __nv_bfloat16* __restrict__ Bh, const __nv_bfloat16* __restrict__ Bl,
    float* __restrict__ C,
    __nv_bfloat16* __restrict__ Ch, __nv_bfloat16* __restrict__ Cl,
    int M, int N, int K, int mode)
{
    const int tid = threadIdx.x;
    const int warp = tid >> 5, lane = tid & 31;
    const int warpM = warp >> 2, warpN = warp & 3;
    const int row0 = blockIdx.y * 128, col0 = blockIdx.x * 128;
    const uint32_t smem_base = (uint32_t)__cvta_generic_to_shared(smem_raw);

    float acc[4][4][4];
    #pragma unroll
    for (int m = 0; m < 4; m++)
        #pragma unroll
        for (int n = 0; n < 4; n++)
            #pragma unroll
            for (int r = 0; r < 4; r++) acc[m][n][r] = 0.f;

    const int KT = K / 32;
    gemm_load_stage(smem_base, tid, row0, col0, 0, K, N, Ah, Al, Bh, Bl);
    if (KT > 1)
        gemm_load_stage(smem_base + 32768, tid, row0, col0, 32, K, N, Ah, Al, Bh, Bl);
    if (KT > 2)
        gemm_load_stage(smem_base + 65536, tid, row0, col0, 64, K, N, Ah, Al, Bh, Bl);

    for (int kt = 0; kt < KT; kt++) {
        const int rem = KT - 1 - kt;
        if (rem >= 2)      { CP_WAIT2(); }
        else if (rem == 1) { CP_WAIT1(); }
        else               { CP_WAIT0(); }
        __syncthreads();
        const uint32_t sb = smem_base + (kt % 3) * 32768;

        #pragma unroll
        for (int ks = 0; ks < 2; ks++) {
            // B fragments: x4.trans loads an n-pair per plane
            uint32_t bfr[2][4][2];
            const int rB = ks * 16 + (lane & 15);
            const int gB = lane >> 4;                 // 0,1 -> within pair
            #pragma unroll
            for (int p = 0; p < 2; p++) {
                #pragma unroll
                for (int np = 0; np < 2; np++) {
                    const int chunk = warpN * 4 + np * 2 + gB;
                    uint32_t addr = sb + 16384 + p * 8192 + rB * 256
                                  + ((chunk ^ (rB & 7)) << 4);
                    asm volatile(
                        "ldmatrix.sync.aligned.m8n8.x4.trans.shared.b16 "
                        "{%0,%1,%2,%3}, [%4];"
                        : "=r"(bfr[p][np * 2][0]),     "=r"(bfr[p][np * 2][1]),
                          "=r"(bfr[p][np * 2 + 1][0]), "=r"(bfr[p][np * 2 + 1][1])
                        : "r"(addr));
                }
            }
            #pragma unroll
            for (int m = 0; m < 4; m++) {
                uint32_t afr[2][4];
                const int rA = warpM * 64 + m * 16 + (lane & 15);
                const int chA = ks * 2 + (lane >> 4);
                #pragma unroll
                for (int p = 0; p < 2; p++) {
                    uint32_t addr = sb + p * 8192 + rA * 64
                                  + ((chA ^ (rA & 3)) << 4);
                    asm volatile(
                        "ldmatrix.sync.aligned.m8n8.x4.shared.b16 {%0,%1,%2,%3}, [%4];"
                        : "=r"(afr[p][0]), "=r"(afr[p][1]),
                          "=r"(afr[p][2]), "=r"(afr[p][3]) : "r"(addr));
                }
                #pragma unroll
                for (int n = 0; n < 4; n++) {
                    mma_bf16(acc[m][n], afr[0], bfr[0][n]);
                    mma_bf16(acc[m][n], afr[0], bfr[1][n]);
                    mma_bf16(acc[m][n], afr[1], bfr[0][n]);
                }
            }
        }
        __syncthreads();
        if (kt + 3 < KT)
            gemm_load_stage(sb, tid, row0, col0, (kt + 3) * 32, K, N, Ah, Al, Bh, Bl);
    }

    #pragma unroll
    for (int m = 0; m < 4; m++) {
        #pragma unroll
        for (int n = 0; n < 4; n++) {
            const int r = row0 + warpM * 64 + m * 16 + (lane >> 2);
            const int c = col0 + warpN * 32 + n * 8 + (lane & 3) * 2;
            if (mode == 0) {
                *(float2*)(C + (size_t)r * N + c) =
                    make_float2(acc[m][n][0], acc[m][n][1]);
                *(float2*)(C + (size_t)(r + 8) * N + c) =
                    make_float2(acc[m][n][2], acc[m][n][3]);
            } else {
                uint32_t h0, l0, h1, l1;
                split_pack(acc[m][n][0], acc[m][n][1], h0, l0);
                split_pack(acc[m][n][2], acc[m][n][3], h1, l1);
                *(uint32_t*)(Ch + (size_t)r * N + c)       = h0;
                *(uint32_t*)(Cl + (size_t)r * N + c)       = l0;
                *(uint32_t*)(Ch + (size_t)(r + 8) * N + c) = h1;
                *(uint32_t*)(Cl + (size_t)(r + 8) * N + c) = l1;
            }
        }
    }
}

// ---------------------------------------------------------------------------
// Tensor-core flash attention (causal), bf16 hi/lo split.
// grid = (16, B*H), block = 128 (4 warps). CTA = 128 q rows, warp = 32 rows.
// Key tiles of 64, cp.async double-buffered. x4 ldmatrix for K/V fragments.
// smem: Qh[128][64] @0, Ql @16384, stages @32768 + s*32768:
//       {Kh @0, Kl @8192, Vh @16384, Vl @24576}, rows 128B, swizzle ch^(r&7).
// ---------------------------------------------------------------------------
__device__ __forceinline__ void attn_load_kv(
    uint32_t stage, int tid, int b, int h0, int j0,
    const __nv_bfloat16* __restrict__ qkvh,
    const __nv_bfloat16* __restrict__ qkvl)
{
    #pragma unroll
    for (int i = 0; i < 16; i++) {
        int idx = tid + i * 128;
        int field = idx >> 9;             // 0:Kh 1:Kl 2:Vh 3:Vl
        int rem = idx & 511;
        int r = rem >> 3, ch = rem & 7;
        const __nv_bfloat16* src = (field & 1) ? qkvl : qkvh;
        int col = ((field >> 1) ? 2048 : 1024) + h0 * 64 + ch * 8;
        const __nv_bfloat16* gp = src + ((size_t)(b * TT + j0 + r)) * 3072 + col;
        uint32_t off = stage + field * 8192 + r * 128 + ((ch ^ (r & 7)) << 4);
        CP_ASYNC16(off, gp);
    }
}

__global__ __launch_bounds__(128) void attn_mma_kernel(
    const __nv_bfloat16* __restrict__ qkvh,
    const __nv_bfloat16* __restrict__ qkvl,
    __nv_bfloat16* __restrict__ outh, __nv_bfloat16* __restrict__ outl)
{
    const int tid = threadIdx.x;
    const int warp = tid >> 5, lane = tid & 31;
    const int b = blockIdx.y >> 4;
    const int h0 = blockIdx.y & 15;
    const int qb = gridDim.x - 1 - blockIdx.x;     // heavy blocks first
    const int qbase = qb * 128;
    const uint32_t smem_base = (uint32_t)__cvta_generic_to_shared(smem_raw);

    #pragma unroll
    for (int i = 0; i < 16; i++) {
        int idx = tid + i * 128;
        int plane = idx >> 10;
        int rem = idx & 1023;
        int r = rem >> 3, ch = rem & 7;
        const __nv_bfloat16* src = plane ? qkvl : qkvh;
        const __nv_bfloat16* gp =
            src + ((size_t)(b * TT + qbase + r)) * 3072 + h0 * 64 + ch * 8;
        uint32_t off = smem_base + plane * 16384 + r * 128 + ((ch ^ (r & 7)) << 4);
        CP_ASYNC16(off, gp);
    }
    const int nkb = 2 * (qb + 1);
    attn_load_kv(smem_base + 32768, tid, b, h0, 0, qkvh, qkvl);
    CP_COMMIT();
    if (nkb > 1) attn_load_kv(smem_base + 65536, tid, b, h0, 64, qkvh, qkvl);
    CP_COMMIT();

    uint32_t qf[2][2][4][4];
    float o[2][8][4];
    float mrow[2][2], lrow[2][2];
    #pragma unroll
    for (int m = 0; m < 2; m++) {
        #pragma unroll
        for (int n = 0; n < 8; n++)
            #pragma unroll
            for (int c = 0; c < 4; c++) o[m][n][c] = 0.f;
        mrow[m][0] = mrow[m][1] = -3.0e38f;
        lrow[m][0] = lrow[m][1] = 0.f;
    }

    const int rbase = qbase + warp * 32;

    for (int kb = 0; kb < nkb; kb++) {
        if (kb + 1 < nkb) { CP_WAIT1(); } else { CP_WAIT0(); }
        __syncthreads();

        if (kb == 0) {
            #pragma unroll
            for (int p = 0; p < 2; p++)
                #pragma unroll
                for (int m = 0; m < 2; m++) {
                    const int rA = warp * 32 + m * 16 + (lane & 15);
                    #pragma unroll
                    for (int kt = 0; kt < 4; kt++) {
                        const int ch = kt * 2 + (lane >> 4);
                        uint32_t addr = smem_base + p * 16384 + rA * 128
                                      + ((ch ^ (rA & 7)) << 4);
                        asm volatile(
                            "ldmatrix.sync.aligned.m8n8.x4.shared.b16 "
                            "{%0,%1,%2,%3}, [%4];"
                            : "=r"(qf[p][m][kt][0]), "=r"(qf[p][m][kt][1]),
                              "=r"(qf[p][m][kt][2]), "=r"(qf[p][m][kt][3])
                            : "r"(addr));
                    }
                }
        }

        const uint32_t sk = smem_base + 32768 + (kb & 1) * 32768;
        const int j0 = kb * 64;

        float acc[2][8][4];
        #pragma unroll
        for (int m = 0; m < 2; m++)
            #pragma unroll
            for (int n = 0; n < 8; n++)
                #pragma unroll
                for (int c = 0; c < 4; c++) acc[m][n][c] = 0.f;

        // ---- S = Q @ K^T, x4 K loads (n-pairs) ----
        const int gK = lane >> 3;                    // 0..3
        #pragma unroll
        for (int kt = 0; kt < 4; kt++) {
            #pragma unroll
            for (int np = 0; np < 4; np++) {
                uint32_t kh[2][2], kl[2][2];
                const int row = (np * 2 + (gK >> 1)) * 8 + (lane & 7);
                const int ch = kt * 2 + (gK & 1);
                uint32_t a0 = sk + row * 128 + ((ch ^ (row & 7)) << 4);
                asm volatile(
                    "ldmatrix.sync.aligned.m8n8.x4.shared.b16 {%0,%1,%2,%3}, [%4];"
                    : "=r"(kh[0][0]), "=r"(kh[0][1]), "=r"(kh[1][0]), "=r"(kh[1][1])
                    : "r"(a0));
                asm volatile(
                    "ldmatrix.sync.aligned.m8n8.x4.shared.b16 {%0,%1,%2,%3}, [%4];"
                    : "=r"(kl[0][0]), "=r"(kl[0][1]), "=r"(kl[1][0]), "=r"(kl[1][1])
                    : "r"(a0 + 8192));
                #pragma unroll
                for (int nn = 0; nn < 2; nn++) {
                    const int n = np * 2 + nn;
                    #pragma unroll
                    for (int m = 0; m < 2; m++) {
                        mma_bf16(acc[m][n], qf[0][m][kt], kh[nn]);
                        mma_bf16(acc[m][n], qf[0][m][kt], kl[nn]);
                        mma_bf16(acc[m][n], qf[1][m][kt], kh[nn]);
                    }
                }
            }
        }

        const bool diag = (j0 >= qbase);
        #pragma unroll
        for (int m = 0; m < 2; m++)
            #pragma unroll
            for (int n = 0; n < 8; n++)
                #pragma unroll
                for (int c = 0; c < 4; c++) {
                    float v = acc[m][n][c] * 0.125f;
                    if (diag) {
                        int col = j0 + n * 8 + ((lane & 3) << 1) + (c & 1);
                        int row = rbase + m * 16 + (lane >> 2) + ((c >> 1) << 3);
                        if (col > row) v = -1e30f;
                    }
                    acc[m][n][c] = v;
                }

        #pragma unroll
        for (int m = 0; m < 2; m++) {
            #pragma unroll
            for (int h = 0; h < 2; h++) {
                float mt = mrow[m][h];
                #pragma unroll
                for (int n = 0; n < 8; n++)
                    mt = fmaxf(mt, fmaxf(acc[m][n][2 * h], acc[m][n][2 * h + 1]));
                mt = fmaxf(mt, __shfl_xor_sync(0xffffffffu, mt, 1));
                mt = fmaxf(mt, __shfl_xor_sync(0xffffffffu, mt, 2));
                float rs = __expf(mrow[m][h] - mt);
                mrow[m][h] = mt;
                float lsum = 0.f;
                #pragma unroll
                for (int n = 0; n < 8; n++) {
                    float p0 = __expf(acc[m][n][2 * h]     - mt);
                    float p1 = __expf(acc[m][n][2 * h + 1] - mt);
                    acc[m][n][2 * h]     = p0;
                    acc[m][n][2 * h + 1] = p1;
                    lsum += p0 + p1;
                    o[m][n][2 * h]     *= rs;
                    o[m][n][2 * h + 1] *= rs;
                }
                lrow[m][h] = lrow[m][h] * rs + lsum;
            }
        }

        // ---- O += P @ V, x4.trans V loads (n-pairs) ----
        #pragma unroll
        for (int kt = 0; kt < 4; kt++) {
            uint32_t pah[2][4], pal[2][4];
            #pragma unroll
            for (int m = 0; m < 2; m++) {
                split_pack(acc[m][2 * kt][0],     acc[m][2 * kt][1],     pah[m][0], pal[m][0]);
                split_pack(acc[m][2 * kt][2],     acc[m][2 * kt][3],     pah[m][1], pal[m][1]);
                split_pack(acc[m][2 * kt + 1][0], acc[m][2 * kt + 1][1], pah[m][2], pal[m][2]);
                split_pack(acc[m][2 * kt + 1][2], acc[m][2 * kt + 1][3], pah[m][3], pal[m][3]);
            }
            const int rV = kt * 16 + (lane & 15);
            const int gV = lane >> 4;
            #pragma unroll
            for (int np = 0; np < 4; np++) {
                uint32_t vh[2][2], vl[2][2];
                const int ch = np * 2 + gV;
                uint32_t a0 = sk + 16384 + rV * 128 + ((ch ^ (rV & 7)) << 4);
                asm volatile(
                    "ldmatrix.sync.aligned.m8n8.x4.trans.shared.b16 {%0,%1,%2,%3}, [%4];"
                    : "=r"(vh[0][0]), "=r"(vh[0][1]), "=r"(vh[1][0]), "=r"(vh[1][1])
                    : "r"(a0));
                asm volatile(
                    "ldmatrix.sync.aligned.m8n8.x4.trans.shared.b16 {%0,%1,%2,%3}, [%4];"
                    : "=r"(vl[0][0]), "=r"(vl[0][1]), "=r"(vl[1][0]), "=r"(vl[1][1])
                    : "r"(a0 + 8192));
                #pragma unroll
                for (int nn = 0; nn < 2; nn++) {
                    const int n = np * 2 + nn;
                    #pragma unroll
                    for (int m = 0; m < 2; m++) {
                        mma_bf16(o[m][n], pah[m], vh[nn]);
                        mma_bf16(o[m][n], pal[m], vh[nn]);
                        mma_bf16(o[m][n], pah[m], vl[nn]);
                    }
                }
            }
        }

        __syncthreads();
        if (kb + 2 < nkb) {
            attn_load_kv(smem_base + 32768 + (kb & 1) * 32768, tid, b, h0,
                         (kb + 2) * 64, qkvh, qkvl);
            CP_COMMIT();
        }
    }

    float inv[2][2];
    #pragma unroll
    for (int m = 0; m < 2; m++)
        #pragma unroll
        for (int h = 0; h < 2; h++) {
            float lt = lrow[m][h];
            lt += __shfl_xor_sync(0xffffffffu, lt, 1);
            lt += __shfl_xor_sync(0xffffffffu, lt, 2);
            inv[m][h] = 1.f / lt;
        }

    #pragma unroll
    for (int m = 0; m < 2; m++) {
        const int r0 = rbase + m * 16 + (lane >> 2);
        #pragma unroll
        for (int n = 0; n < 8; n++) {
            const int cd = h0 * 64 + n * 8 + ((lane & 3) << 1);
            uint32_t h_, l_;
            split_pack(o[m][n][0] * inv[m][0], o[m][n][1] * inv[m][0], h_, l_);
            size_t base0 = (size_t)(b * TT + r0) * 1024 + cd;
            *(uint32_t*)(outh + base0) = h_;
            *(uint32_t*)(outl + base0) = l_;
            split_pack(o[m][n][2] * inv[m][1], o[m][n][3] * inv[m][1], h_, l_);
            size_t base1 = (size_t)(b * TT + r0 + 8) * 1024 + cd;
            *(uint32_t*)(outh + base1) = h_;
            *(uint32_t*)(outl + base1) = l_;
        }
    }
}

// ---------------------------------------------------------------------------
extern "C" void kernel_launch(void* const* d_in, const int* in_sizes, int n_in,
                              void* d_out, int out_size)
{
    const float* x    = (const float*)d_in[0];
    const float* Wqkv = (const float*)d_in[1];
    const float* Wout = (const float*)d_in[2];
    float* out = (float*)d_out;

    __nv_bfloat16 *qkvh, *qkvl, *xh, *xl, *wqh, *wql, *woh, *wol, *ah, *al;
    cudaGetSymbolAddress((void**)&qkvh, g_qkvh); cudaGetSymbolAddress((void**)&qkvl, g_qkvl);
    cudaGetSymbolAddress((void**)&xh, g_xh);     cudaGetSymbolAddress((void**)&xl, g_xl);
    cudaGetSymbolAddress((void**)&wqh, g_wqh);   cudaGetSymbolAddress((void**)&wql, g_wql);
    cudaGetSymbolAddress((void**)&woh, g_woh);   cudaGetSymbolAddress((void**)&wol, g_wol);
    cudaGetSymbolAddress((void**)&ah, g_ah);     cudaGetSymbolAddress((void**)&al, g_al);

    cudaFuncSetAttribute(gemm_split_kernel,
                         cudaFuncAttributeMaxDynamicSharedMemorySize, 98304);
    cudaFuncSetAttribute(attn_mma_kernel,
                         cudaFuncAttributeMaxDynamicSharedMemorySize, 98304);

    const int M = TB * TT;            // 4096
    const int nx  = M * TC;
    const int nwq = TC * 3 * TC;
    const int nwo = TC * TC;

    split_kernel<<<nx  / 1024, 256>>>(x, xh, xl, nx);
    split_kernel<<<nwq / 1024, 256>>>(Wqkv, wqh, wql, nwq);
    split_kernel<<<nwo / 1024, 256>>>(Wout, woh, wol, nwo);

    // 1) QKV projection -> bf16 hi/lo planes
    gemm_split_kernel<<<dim3((3 * TC) / 128, M / 128), 256, 98304>>>(
        xh, xl, wqh, wql, nullptr, qkvh, qkvl, M, 3 * TC, TC, 1);

    // 2) Tensor-core causal flash attention -> bf16 hi/lo planes
    attn_mma_kernel<<<dim3(TT / 128, TB * TH), 128, 98304>>>(qkvh, qkvl, ah, al);

    // 3) Output projection -> fp32 out
    gemm_split_kernel<<<dim3(TC / 128, M / 128), 256, 98304>>>(
        ah, al, woh, wol, out, nullptr, nullptr, M, TC, TC, 0);
}

// round 10
// speedup vs baseline: 3.7961x; 1.1205x over previous
#include <cuda_runtime.h>
#include <cuda_bf16.h>
#include <cstdint>
#include <cstddef>

// Problem constants
#define TB 2
#define TT 2048
#define TC 1024
#define TH 16
#define TD 64

// ---------------------------------------------------------------------------
// Scratch (__device__ globals; allocation-free rule)
// ---------------------------------------------------------------------------
__device__ __align__(256) __nv_bfloat16 g_qkvh[(size_t)TB * TT * 3 * TC];
__device__ __align__(256) __nv_bfloat16 g_qkvl[(size_t)TB * TT * 3 * TC];
__device__ __align__(256) __nv_bfloat16 g_xh[(size_t)TB * TT * TC];
__device__ __align__(256) __nv_bfloat16 g_xl[(size_t)TB * TT * TC];
__device__ __align__(256) __nv_bfloat16 g_wqh[(size_t)TC * 3 * TC];
__device__ __align__(256) __nv_bfloat16 g_wql[(size_t)TC * 3 * TC];
__device__ __align__(256) __nv_bfloat16 g_woh[(size_t)TC * TC];
__device__ __align__(256) __nv_bfloat16 g_wol[(size_t)TC * TC];
__device__ __align__(256) __nv_bfloat16 g_ah[(size_t)TB * TT * TC];
__device__ __align__(256) __nv_bfloat16 g_al[(size_t)TB * TT * TC];

// ---------------------------------------------------------------------------
__device__ __forceinline__ void split_pack(float x, float y,
                                           uint32_t& hi, uint32_t& lo)
{
    __nv_bfloat162 h = __float22bfloat162_rn(make_float2(x, y));
    float hx = __bfloat162float(h.x), hy = __bfloat162float(h.y);
    __nv_bfloat162 l = __float22bfloat162_rn(make_float2(x - hx, y - hy));
    hi = *(uint32_t*)&h;
    lo = *(uint32_t*)&l;
}

__device__ __forceinline__ void mma_bf16(float* d, const uint32_t* a,
                                         const uint32_t* b)
{
    asm volatile(
        "mma.sync.aligned.m16n8k16.row.col.f32.bf16.bf16.f32 "
        "{%0,%1,%2,%3}, {%4,%5,%6,%7}, {%8,%9}, {%0,%1,%2,%3};"
        : "+f"(d[0]), "+f"(d[1]), "+f"(d[2]), "+f"(d[3])
        : "r"(a[0]), "r"(a[1]), "r"(a[2]), "r"(a[3]), "r"(b[0]), "r"(b[1]));
}

// ---------------------------------------------------------------------------
// Fused split: x, Wqkv, Wout fp32 -> bf16 hi/lo planes, one launch.
// ---------------------------------------------------------------------------
__device__ __forceinline__ void split4(const float* __restrict__ in,
                                       __nv_bfloat16* __restrict__ hi,
                                       __nv_bfloat16* __restrict__ lo, int i)
{
    float4 v = *(const float4*)(in + i);
    uint32_t h0, l0, h1, l1;
    split_pack(v.x, v.y, h0, l0);
    split_pack(v.z, v.w, h1, l1);
    uint32_t* hp = (uint32_t*)(hi + i);
    uint32_t* lp = (uint32_t*)(lo + i);
    hp[0] = h0; hp[1] = h1;
    lp[0] = l0; lp[1] = l1;
}

#define NX  (TB * TT * TC)          // 4194304
#define NWQ (TC * 3 * TC)           // 3145728
#define NWO (TC * TC)               // 1048576

__global__ void split3_kernel(
    const float* __restrict__ x,  const float* __restrict__ wq,
    const float* __restrict__ wo,
    __nv_bfloat16* __restrict__ xh,  __nv_bfloat16* __restrict__ xl,
    __nv_bfloat16* __restrict__ wqh, __nv_bfloat16* __restrict__ wql,
    __nv_bfloat16* __restrict__ woh, __nv_bfloat16* __restrict__ wol)
{
    int i = (blockIdx.x * blockDim.x + threadIdx.x) * 4;
    if (i < NX) {
        split4(x, xh, xl, i);
    } else if (i < NX + NWQ) {
        split4(wq, wqh, wql, i - NX);
    } else if (i < NX + NWQ + NWO) {
        split4(wo, woh, wol, i - NX - NWQ);
    }
}

// ---------------------------------------------------------------------------
// Persistent split-bf16 GEMM: C[M,N] (fp32) = (Ah+Al)[M,K] @ (Bh+Bl)[K,N]
// acc = Ah*Bh + Ah*Bl + Al*Bh.  BM=BN=128, BK=32, 256 threads
// (8 warps: 2(M) x 4(N), warp tile 64x32).  3-stage cp.async pipeline.
// Grid-stride tile loop (grid = 296 = 2 CTAs x 148 SMs).
// mode 0: fp32 C.  mode 1: bf16 hi/lo planes Ch/Cl.
// stage layout (32KB): Ah@0 Al@8K Bh@16K Bl@24K
// ---------------------------------------------------------------------------
#define CP_ASYNC16(dst, src) \
    asm volatile("cp.async.cg.shared.global [%0], [%1], 16;\n" :: "r"(dst), "l"(src))
#define CP_COMMIT() asm volatile("cp.async.commit_group;\n" ::)
#define CP_WAIT2()  asm volatile("cp.async.wait_group 2;\n" ::)
#define CP_WAIT1()  asm volatile("cp.async.wait_group 1;\n" ::)
#define CP_WAIT0()  asm volatile("cp.async.wait_group 0;\n" ::)

__device__ __forceinline__ void gemm_load_stage(
    uint32_t sb, int tid, int row0, int col0, int k0, int K, int N,
    const __nv_bfloat16* __restrict__ Ah, const __nv_bfloat16* __restrict__ Al,
    const __nv_bfloat16* __restrict__ Bh, const __nv_bfloat16* __restrict__ Bl)
{
    #pragma unroll
    for (int i = 0; i < 2; i++) {
        int idx = tid + i * 256;
        int ra = idx >> 2, ca = idx & 3;
        uint32_t offa = ra * 64 + ((ca ^ (ra & 3)) << 4);
        size_t ga = (size_t)(row0 + ra) * K + k0 + ca * 8;
        CP_ASYNC16(sb + offa,        Ah + ga);
        CP_ASYNC16(sb + 8192 + offa, Al + ga);
        int rb = idx >> 4, cb = idx & 15;
        uint32_t offb = rb * 256 + ((cb ^ (rb & 7)) << 4);
        size_t gb = (size_t)(k0 + rb) * N + col0 + cb * 8;
        CP_ASYNC16(sb + 16384 + offb, Bh + gb);
        CP_ASYNC16(sb + 24576 + offb, Bl + gb);
    }
    CP_COMMIT();
}

extern __shared__ __align__(1024) char smem_raw[];

__global__ __launch_bounds__(256) void gemm_split_kernel(
    const __nv_bfloat16* __restrict__ Ah, const __nv_bfloat16* __restrict__ Al,
    const __nv_bfloat16* __restrict__ Bh, const __nv_bfloat16* __restrict__ Bl,
    float* __restrict__ C,
    __nv_bfloat16* __restrict__ Ch, __nv_bfloat16* __restrict__ Cl,
    int M, int N, int K, int mode)
{
    const int tid = threadIdx.x;
    const int warp = tid >> 5, lane = tid & 31;
    const int warpM = warp >> 2, warpN = warp & 3;
    const uint32_t smem_base = (uint32_t)__cvta_generic_to_shared(smem_raw);
    const int tiles_x = N >> 7;
    const int tiles = (M >> 7) * tiles_x;
    const int KT = K / 32;

    for (int t = blockIdx.x; t < tiles; t += gridDim.x) {
        const int row0 = (t / tiles_x) << 7;
        const int col0 = (t % tiles_x) << 7;

        __syncthreads();   // previous tile's smem fully consumed

        float acc[4][4][4];
        #pragma unroll
        for (int m = 0; m < 4; m++)
            #pragma unroll
            for (int n = 0; n < 4; n++)
                #pragma unroll
                for (int r = 0; r < 4; r++) acc[m][n][r] = 0.f;

        gemm_load_stage(smem_base, tid, row0, col0, 0, K, N, Ah, Al, Bh, Bl);
        gemm_load_stage(smem_base + 32768, tid, row0, col0, 32, K, N, Ah, Al, Bh, Bl);
        gemm_load_stage(smem_base + 65536, tid, row0, col0, 64, K, N, Ah, Al, Bh, Bl);

        for (int kt = 0; kt < KT; kt++) {
            const int rem = KT - 1 - kt;
            if (rem >= 2)      { CP_WAIT2(); }
            else if (rem == 1) { CP_WAIT1(); }
            else               { CP_WAIT0(); }
            __syncthreads();
            const uint32_t sb = smem_base + (kt % 3) * 32768;

            #pragma unroll
            for (int ks = 0; ks < 2; ks++) {
                uint32_t bfr[2][4][2];
                const int rB = ks * 16 + (lane & 15);
                const int gB = lane >> 4;
                #pragma unroll
                for (int p = 0; p < 2; p++) {
                    #pragma unroll
                    for (int np = 0; np < 2; np++) {
                        const int chunk = warpN * 4 + np * 2 + gB;
                        uint32_t addr = sb + 16384 + p * 8192 + rB * 256
                                      + ((chunk ^ (rB & 7)) << 4);
                        asm volatile(
                            "ldmatrix.sync.aligned.m8n8.x4.trans.shared.b16 "
                            "{%0,%1,%2,%3}, [%4];"
                            : "=r"(bfr[p][np * 2][0]),     "=r"(bfr[p][np * 2][1]),
                              "=r"(bfr[p][np * 2 + 1][0]), "=r"(bfr[p][np * 2 + 1][1])
                            : "r"(addr));
                    }
                }
                #pragma unroll
                for (int m = 0; m < 4; m++) {
                    uint32_t afr[2][4];
                    const int rA = warpM * 64 + m * 16 + (lane & 15);
                    const int chA = ks * 2 + (lane >> 4);
                    #pragma unroll
                    for (int p = 0; p < 2; p++) {
                        uint32_t addr = sb + p * 8192 + rA * 64
                                      + ((chA ^ (rA & 3)) << 4);
                        asm volatile(
                            "ldmatrix.sync.aligned.m8n8.x4.shared.b16 {%0,%1,%2,%3}, [%4];"
                            : "=r"(afr[p][0]), "=r"(afr[p][1]),
                              "=r"(afr[p][2]), "=r"(afr[p][3]) : "r"(addr));
                    }
                    #pragma unroll
                    for (int n = 0; n < 4; n++) {
                        mma_bf16(acc[m][n], afr[0], bfr[0][n]);
                        mma_bf16(acc[m][n], afr[0], bfr[1][n]);
                        mma_bf16(acc[m][n], afr[1], bfr[0][n]);
                    }
                }
            }
            __syncthreads();
            if (kt + 3 < KT)
                gemm_load_stage(sb, tid, row0, col0, (kt + 3) * 32, K, N,
                                Ah, Al, Bh, Bl);
        }

        #pragma unroll
        for (int m = 0; m < 4; m++) {
            #pragma unroll
            for (int n = 0; n < 4; n++) {
                const int r = row0 + warpM * 64 + m * 16 + (lane >> 2);
                const int c = col0 + warpN * 32 + n * 8 + (lane & 3) * 2;
                if (mode == 0) {
                    *(float2*)(C + (size_t)r * N + c) =
                        make_float2(acc[m][n][0], acc[m][n][1]);
                    *(float2*)(C + (size_t)(r + 8) * N + c) =
                        make_float2(acc[m][n][2], acc[m][n][3]);
                } else {
                    uint32_t h0, l0, h1, l1;
                    split_pack(acc[m][n][0], acc[m][n][1], h0, l0);
                    split_pack(acc[m][n][2], acc[m][n][3], h1, l1);
                    *(uint32_t*)(Ch + (size_t)r * N + c)       = h0;
                    *(uint32_t*)(Cl + (size_t)r * N + c)       = l0;
                    *(uint32_t*)(Ch + (size_t)(r + 8) * N + c) = h1;
                    *(uint32_t*)(Cl + (size_t)(r + 8) * N + c) = l1;
                }
            }
        }
    }
}

// ---------------------------------------------------------------------------
// Persistent tensor-core flash attention (causal), bf16 hi/lo split.
// grid = 296, block = 128 (4 warps). Snake-scheduled heavy-first tiles:
// heavy rank r -> qb = 15 - (r>>5), bh = r&31.  CTA b processes ranks
// b, 2G-1-b, ... (G = gridDim) => per-CTA work bounded near the mean.
// Key tiles of 64, cp.async double-buffered. x4 ldmatrix for K/V fragments.
// smem: Qh[128][64] @0, Ql @16384, stages @32768 + s*32768:
//       {Kh @0, Kl @8192, Vh @16384, Vl @24576}, rows 128B, swizzle ch^(r&7).
// ---------------------------------------------------------------------------
__device__ __forceinline__ void attn_load_kv(
    uint32_t stage, int tid, int b, int h0, int j0,
    const __nv_bfloat16* __restrict__ qkvh,
    const __nv_bfloat16* __restrict__ qkvl)
{
    #pragma unroll
    for (int i = 0; i < 16; i++) {
        int idx = tid + i * 128;
        int field = idx >> 9;             // 0:Kh 1:Kl 2:Vh 3:Vl
        int rem = idx & 511;
        int r = rem >> 3, ch = rem & 7;
        const __nv_bfloat16* src = (field & 1) ? qkvl : qkvh;
        int col = ((field >> 1) ? 2048 : 1024) + h0 * 64 + ch * 8;
        const __nv_bfloat16* gp = src + ((size_t)(b * TT + j0 + r)) * 3072 + col;
        uint32_t off = stage + field * 8192 + r * 128 + ((ch ^ (r & 7)) << 4);
        CP_ASYNC16(off, gp);
    }
}

#define ATT_NT 512   // 16 q-blocks * 32 (b,h)

__global__ __launch_bounds__(128) void attn_mma_kernel(
    const __nv_bfloat16* __restrict__ qkvh,
    const __nv_bfloat16* __restrict__ qkvl,
    __nv_bfloat16* __restrict__ outh, __nv_bfloat16* __restrict__ outl)
{
    const int tid = threadIdx.x;
    const int warp = tid >> 5, lane = tid & 31;
    const uint32_t smem_base = (uint32_t)__cvta_generic_to_shared(smem_raw);
    const int G = gridDim.x;

    for (int p = 0;; p++) {
        const int rk = p * G + ((p & 1) ? (G - 1 - (int)blockIdx.x)
                                        : (int)blockIdx.x);
        if (rk >= ATT_NT) break;
        const int qb = 15 - (rk >> 5);
        const int bh = rk & 31;
        const int b = bh >> 4;
        const int h0 = bh & 15;
        const int qbase = qb * 128;

        __syncthreads();   // previous tile's smem fully consumed

        // --- Q tile (both planes) + first KV stages ---
        #pragma unroll
        for (int i = 0; i < 16; i++) {
            int idx = tid + i * 128;
            int plane = idx >> 10;
            int rem = idx & 1023;
            int r = rem >> 3, ch = rem & 7;
            const __nv_bfloat16* src = plane ? qkvl : qkvh;
            const __nv_bfloat16* gp =
                src + ((size_t)(b * TT + qbase + r)) * 3072 + h0 * 64 + ch * 8;
            uint32_t off = smem_base + plane * 16384 + r * 128
                         + ((ch ^ (r & 7)) << 4);
            CP_ASYNC16(off, gp);
        }
        const int nkb = 2 * (qb + 1);
        attn_load_kv(smem_base + 32768, tid, b, h0, 0, qkvh, qkvl);
        CP_COMMIT();
        if (nkb > 1) attn_load_kv(smem_base + 65536, tid, b, h0, 64, qkvh, qkvl);
        CP_COMMIT();

        uint32_t qf[2][2][4][4];
        float o[2][8][4];
        float mrow[2][2], lrow[2][2];
        #pragma unroll
        for (int m = 0; m < 2; m++) {
            #pragma unroll
            for (int n = 0; n < 8; n++)
                #pragma unroll
                for (int c = 0; c < 4; c++) o[m][n][c] = 0.f;
            mrow[m][0] = mrow[m][1] = -3.0e38f;
            lrow[m][0] = lrow[m][1] = 0.f;
        }

        const int rbase = qbase + warp * 32;

        for (int kb = 0; kb < nkb; kb++) {
            if (kb + 1 < nkb) { CP_WAIT1(); } else { CP_WAIT0(); }
            __syncthreads();

            if (kb == 0) {
                #pragma unroll
                for (int pp = 0; pp < 2; pp++)
                    #pragma unroll
                    for (int m = 0; m < 2; m++) {
                        const int rA = warp * 32 + m * 16 + (lane & 15);
                        #pragma unroll
                        for (int kt = 0; kt < 4; kt++) {
                            const int ch = kt * 2 + (lane >> 4);
                            uint32_t addr = smem_base + pp * 16384 + rA * 128
                                          + ((ch ^ (rA & 7)) << 4);
                            asm volatile(
                                "ldmatrix.sync.aligned.m8n8.x4.shared.b16 "
                                "{%0,%1,%2,%3}, [%4];"
                                : "=r"(qf[pp][m][kt][0]), "=r"(qf[pp][m][kt][1]),
                                  "=r"(qf[pp][m][kt][2]), "=r"(qf[pp][m][kt][3])
                                : "r"(addr));
                        }
                    }
            }

            const uint32_t sk = smem_base + 32768 + (kb & 1) * 32768;
            const int j0 = kb * 64;

            float acc[2][8][4];
            #pragma unroll
            for (int m = 0; m < 2; m++)
                #pragma unroll
                for (int n = 0; n < 8; n++)
                    #pragma unroll
                    for (int c = 0; c < 4; c++) acc[m][n][c] = 0.f;

            // ---- S = Q @ K^T, x4 K loads (n-pairs) ----
            const int gK = lane >> 3;
            #pragma unroll
            for (int kt = 0; kt < 4; kt++) {
                #pragma unroll
                for (int np = 0; np < 4; np++) {
                    uint32_t kh[2][2], kl[2][2];
                    const int row = (np * 2 + (gK >> 1)) * 8 + (lane & 7);
                    const int ch = kt * 2 + (gK & 1);
                    uint32_t a0 = sk + row * 128 + ((ch ^ (row & 7)) << 4);
                    asm volatile(
                        "ldmatrix.sync.aligned.m8n8.x4.shared.b16 {%0,%1,%2,%3}, [%4];"
                        : "=r"(kh[0][0]), "=r"(kh[0][1]), "=r"(kh[1][0]), "=r"(kh[1][1])
                        : "r"(a0));
                    asm volatile(
                        "ldmatrix.sync.aligned.m8n8.x4.shared.b16 {%0,%1,%2,%3}, [%4];"
                        : "=r"(kl[0][0]), "=r"(kl[0][1]), "=r"(kl[1][0]), "=r"(kl[1][1])
                        : "r"(a0 + 8192));
                    #pragma unroll
                    for (int nn = 0; nn < 2; nn++) {
                        const int n = np * 2 + nn;
                        #pragma unroll
                        for (int m = 0; m < 2; m++) {
                            mma_bf16(acc[m][n], qf[0][m][kt], kh[nn]);
                            mma_bf16(acc[m][n], qf[0][m][kt], kl[nn]);
                            mma_bf16(acc[m][n], qf[1][m][kt], kh[nn]);
                        }
                    }
                }
            }

            const bool diag = (j0 >= qbase);
            #pragma unroll
            for (int m = 0; m < 2; m++)
                #pragma unroll
                for (int n = 0; n < 8; n++)
                    #pragma unroll
                    for (int c = 0; c < 4; c++) {
                        float v = acc[m][n][c] * 0.125f;
                        if (diag) {
                            int col = j0 + n * 8 + ((lane & 3) << 1) + (c & 1);
                            int row = rbase + m * 16 + (lane >> 2) + ((c >> 1) << 3);
                            if (col > row) v = -1e30f;
                        }
                        acc[m][n][c] = v;
                    }

            #pragma unroll
            for (int m = 0; m < 2; m++) {
                #pragma unroll
                for (int h = 0; h < 2; h++) {
                    float mt = mrow[m][h];
                    #pragma unroll
                    for (int n = 0; n < 8; n++)
                        mt = fmaxf(mt, fmaxf(acc[m][n][2 * h], acc[m][n][2 * h + 1]));
                    mt = fmaxf(mt, __shfl_xor_sync(0xffffffffu, mt, 1));
                    mt = fmaxf(mt, __shfl_xor_sync(0xffffffffu, mt, 2));
                    float rs = __expf(mrow[m][h] - mt);
                    mrow[m][h] = mt;
                    float lsum = 0.f;
                    #pragma unroll
                    for (int n = 0; n < 8; n++) {
                        float p0 = __expf(acc[m][n][2 * h]     - mt);
                        float p1 = __expf(acc[m][n][2 * h + 1] - mt);
                        acc[m][n][2 * h]     = p0;
                        acc[m][n][2 * h + 1] = p1;
                        lsum += p0 + p1;
                        o[m][n][2 * h]     *= rs;
                        o[m][n][2 * h + 1] *= rs;
                    }
                    lrow[m][h] = lrow[m][h] * rs + lsum;
                }
            }

            // ---- O += P @ V, x4.trans V loads (n-pairs) ----
            #pragma unroll
            for (int kt = 0; kt < 4; kt++) {
                uint32_t pah[2][4], pal[2][4];
                #pragma unroll
                for (int m = 0; m < 2; m++) {
                    split_pack(acc[m][2 * kt][0],     acc[m][2 * kt][1],     pah[m][0], pal[m][0]);
                    split_pack(acc[m][2 * kt][2],     acc[m][2 * kt][3],     pah[m][1], pal[m][1]);
                    split_pack(acc[m][2 * kt + 1][0], acc[m][2 * kt + 1][1], pah[m][2], pal[m][2]);
                    split_pack(acc[m][2 * kt + 1][2], acc[m][2 * kt + 1][3], pah[m][3], pal[m][3]);
                }
                const int rV = kt * 16 + (lane & 15);
                const int gV = lane >> 4;
                #pragma unroll
                for (int np = 0; np < 4; np++) {
                    uint32_t vh[2][2], vl[2][2];
                    const int ch = np * 2 + gV;
                    uint32_t a0 = sk + 16384 + rV * 128 + ((ch ^ (rV & 7)) << 4);
                    asm volatile(
                        "ldmatrix.sync.aligned.m8n8.x4.trans.shared.b16 {%0,%1,%2,%3}, [%4];"
                        : "=r"(vh[0][0]), "=r"(vh[0][1]), "=r"(vh[1][0]), "=r"(vh[1][1])
                        : "r"(a0));
                    asm volatile(
                        "ldmatrix.sync.aligned.m8n8.x4.trans.shared.b16 {%0,%1,%2,%3}, [%4];"
                        : "=r"(vl[0][0]), "=r"(vl[0][1]), "=r"(vl[1][0]), "=r"(vl[1][1])
                        : "r"(a0 + 8192));
                    #pragma unroll
                    for (int nn = 0; nn < 2; nn++) {
                        const int n = np * 2 + nn;
                        #pragma unroll
                        for (int m = 0; m < 2; m++) {
                            mma_bf16(o[m][n], pah[m], vh[nn]);
                            mma_bf16(o[m][n], pal[m], vh[nn]);
                            mma_bf16(o[m][n], pah[m], vl[nn]);
                        }
                    }
                }
            }

            __syncthreads();
            if (kb + 2 < nkb) {
                attn_load_kv(smem_base + 32768 + (kb & 1) * 32768, tid, b, h0,
                             (kb + 2) * 64, qkvh, qkvl);
                CP_COMMIT();
            }
        }

        float inv[2][2];
        #pragma unroll
        for (int m = 0; m < 2; m++)
            #pragma unroll
            for (int h = 0; h < 2; h++) {
                float lt = lrow[m][h];
                lt += __shfl_xor_sync(0xffffffffu, lt, 1);
                lt += __shfl_xor_sync(0xffffffffu, lt, 2);
                inv[m][h] = 1.f / lt;
            }

        #pragma unroll
        for (int m = 0; m < 2; m++) {
            const int r0 = rbase + m * 16 + (lane >> 2);
            #pragma unroll
            for (int n = 0; n < 8; n++) {
                const int cd = h0 * 64 + n * 8 + ((lane & 3) << 1);
                uint32_t h_, l_;
                split_pack(o[m][n][0] * inv[m][0], o[m][n][1] * inv[m][0], h_, l_);
                size_t base0 = (size_t)(b * TT + r0) * 1024 + cd;
                *(uint32_t*)(outh + base0) = h_;
                *(uint32_t*)(outl + base0) = l_;
                split_pack(o[m][n][2] * inv[m][1], o[m][n][3] * inv[m][1], h_, l_);
                size_t base1 = (size_t)(b * TT + r0 + 8) * 1024 + cd;
                *(uint32_t*)(outh + base1) = h_;
                *(uint32_t*)(outl + base1) = l_;
            }
        }
    }
}

// ---------------------------------------------------------------------------
extern "C" void kernel_launch(void* const* d_in, const int* in_sizes, int n_in,
                              void* d_out, int out_size)
{
    const float* x    = (const float*)d_in[0];
    const float* Wqkv = (const float*)d_in[1];
    const float* Wout = (const float*)d_in[2];
    float* out = (float*)d_out;

    __nv_bfloat16 *qkvh, *qkvl, *xh, *xl, *wqh, *wql, *woh, *wol, *ah, *al;
    cudaGetSymbolAddress((void**)&qkvh, g_qkvh); cudaGetSymbolAddress((void**)&qkvl, g_qkvl);
    cudaGetSymbolAddress((void**)&xh, g_xh);     cudaGetSymbolAddress((void**)&xl, g_xl);
    cudaGetSymbolAddress((void**)&wqh, g_wqh);   cudaGetSymbolAddress((void**)&wql, g_wql);
    cudaGetSymbolAddress((void**)&woh, g_woh);   cudaGetSymbolAddress((void**)&wol, g_wol);
    cudaGetSymbolAddress((void**)&ah, g_ah);     cudaGetSymbolAddress((void**)&al, g_al);

    cudaFuncSetAttribute(gemm_split_kernel,
                         cudaFuncAttributeMaxDynamicSharedMemorySize, 98304);
    cudaFuncSetAttribute(attn_mma_kernel,
                         cudaFuncAttributeMaxDynamicSharedMemorySize, 98304);

    const int M = TB * TT;            // 4096
    const int total4 = (NX + NWQ + NWO) / 4;

    // 0) fused input splits
    split3_kernel<<<(total4 + 255) / 256, 256>>>(x, Wqkv, Wout,
                                                 xh, xl, wqh, wql, woh, wol);

    // 1) QKV projection -> bf16 hi/lo planes (persistent, 768 tiles)
    {
        int tiles = (M / 128) * (3 * TC / 128);
        int grid = tiles < 296 ? tiles : 296;
        gemm_split_kernel<<<grid, 256, 98304>>>(
            xh, xl, wqh, wql, nullptr, qkvh, qkvl, M, 3 * TC, TC, 1);
    }

    // 2) Persistent causal flash attention -> bf16 hi/lo planes
    attn_mma_kernel<<<296, 128, 98304>>>(qkvh, qkvl, ah, al);

    // 3) Output projection -> fp32 out (256 tiles)
    {
        int tiles = (M / 128) * (TC / 128);
        int grid = tiles < 296 ? tiles : 296;
        gemm_split_kernel<<<grid, 256, 98304>>>(
            ah, al, woh, wol, out, nullptr, nullptr, M, TC, TC, 0);
    }
}

// round 15
// speedup vs baseline: 3.8823x; 1.0227x over previous
#include <cuda_runtime.h>
#include <cuda_bf16.h>
#include <cstdint>
#include <cstddef>

// Problem constants
#define TB 2
#define TT 2048
#define TC 1024
#define TH 16
#define TD 64

// ---------------------------------------------------------------------------
// Scratch (__device__ globals; allocation-free rule)
// ---------------------------------------------------------------------------
__device__ __align__(256) __nv_bfloat16 g_qkvh[(size_t)TB * TT * 3 * TC];
__device__ __align__(256) __nv_bfloat16 g_qkvl[(size_t)TB * TT * 3 * TC];
__device__ __align__(256) __nv_bfloat16 g_xh[(size_t)TB * TT * TC];
__device__ __align__(256) __nv_bfloat16 g_xl[(size_t)TB * TT * TC];
__device__ __align__(256) __nv_bfloat16 g_wqh[(size_t)TC * 3 * TC];
__device__ __align__(256) __nv_bfloat16 g_wql[(size_t)TC * 3 * TC];
__device__ __align__(256) __nv_bfloat16 g_woh[(size_t)TC * TC];
__device__ __align__(256) __nv_bfloat16 g_wol[(size_t)TC * TC];
__device__ __align__(256) __nv_bfloat16 g_ah[(size_t)TB * TT * TC];
__device__ __align__(256) __nv_bfloat16 g_al[(size_t)TB * TT * TC];

// ---------------------------------------------------------------------------
__device__ __forceinline__ void split_pack(float x, float y,
                                           uint32_t& hi, uint32_t& lo)
{
    __nv_bfloat162 h = __float22bfloat162_rn(make_float2(x, y));
    float hx = __bfloat162float(h.x), hy = __bfloat162float(h.y);
    __nv_bfloat162 l = __float22bfloat162_rn(make_float2(x - hx, y - hy));
    hi = *(uint32_t*)&h;
    lo = *(uint32_t*)&l;
}

__device__ __forceinline__ void mma_bf16(float* d, const uint32_t* a,
                                         const uint32_t* b)
{
    asm volatile(
        "mma.sync.aligned.m16n8k16.row.col.f32.bf16.bf16.f32 "
        "{%0,%1,%2,%3}, {%4,%5,%6,%7}, {%8,%9}, {%0,%1,%2,%3};"
        : "+f"(d[0]), "+f"(d[1]), "+f"(d[2]), "+f"(d[3])
        : "r"(a[0]), "r"(a[1]), "r"(a[2]), "r"(a[3]), "r"(b[0]), "r"(b[1]));
}

// ---------------------------------------------------------------------------
// Fused split: x, Wqkv, Wout fp32 -> bf16 hi/lo planes, one launch.
// ---------------------------------------------------------------------------
__device__ __forceinline__ void split4(const float* __restrict__ in,
                                       __nv_bfloat16* __restrict__ hi,
                                       __nv_bfloat16* __restrict__ lo, int i)
{
    float4 v = *(const float4*)(in + i);
    uint32_t h0, l0, h1, l1;
    split_pack(v.x, v.y, h0, l0);
    split_pack(v.z, v.w, h1, l1);
    uint32_t* hp = (uint32_t*)(hi + i);
    uint32_t* lp = (uint32_t*)(lo + i);
    hp[0] = h0; hp[1] = h1;
    lp[0] = l0; lp[1] = l1;
}

#define NX  (TB * TT * TC)          // 4194304
#define NWQ (TC * 3 * TC)           // 3145728
#define NWO (TC * TC)               // 1048576

__global__ void split3_kernel(
    const float* __restrict__ x,  const float* __restrict__ wq,
    const float* __restrict__ wo,
    __nv_bfloat16* __restrict__ xh,  __nv_bfloat16* __restrict__ xl,
    __nv_bfloat16* __restrict__ wqh, __nv_bfloat16* __restrict__ wql,
    __nv_bfloat16* __restrict__ woh, __nv_bfloat16* __restrict__ wol)
{
    int i = (blockIdx.x * blockDim.x + threadIdx.x) * 4;
    if (i < NX) {
        split4(x, xh, xl, i);
    } else if (i < NX + NWQ) {
        split4(wq, wqh, wql, i - NX);
    } else if (i < NX + NWQ + NWO) {
        split4(wo, woh, wol, i - NX - NWQ);
    }
}

// ---------------------------------------------------------------------------
// Persistent split-bf16 GEMM: C[M,N] (fp32) = (Ah+Al)[M,K] @ (Bh+Bl)[K,N]
// acc = Ah*Bh + Ah*Bl + Al*Bh.  BM=BN=128, BK=32, 256 threads
// (8 warps: 2(M) x 4(N), warp tile 64x32).
// 3-stage cp.async, single sync per k-iteration (validated in R12/R14 runs).
// Grid-stride tile loop (grid = min(tiles, 296)).
// mode 0: fp32 C.  mode 1: bf16 hi/lo planes Ch/Cl.
// stage layout (32KB): Ah@0 Al@8K Bh@16K Bl@24K
// ---------------------------------------------------------------------------
#define CP_ASYNC16(dst, src) \
    asm volatile("cp.async.cg.shared.global [%0], [%1], 16;\n" :: "r"(dst), "l"(src))
#define CP_COMMIT() asm volatile("cp.async.commit_group;\n" ::)
#define CP_WAIT1()  asm volatile("cp.async.wait_group 1;\n" ::)
#define CP_WAIT0()  asm volatile("cp.async.wait_group 0;\n" ::)

__device__ __forceinline__ void gemm_load_stage(
    uint32_t sb, int tid, int row0, int col0, int k0, int K, int N,
    const __nv_bfloat16* __restrict__ Ah, const __nv_bfloat16* __restrict__ Al,
    const __nv_bfloat16* __restrict__ Bh, const __nv_bfloat16* __restrict__ Bl)
{
    #pragma unroll
    for (int i = 0; i < 2; i++) {
        int idx = tid + i * 256;
        int ra = idx >> 2, ca = idx & 3;
        uint32_t offa = ra * 64 + ((ca ^ (ra & 3)) << 4);
        size_t ga = (size_t)(row0 + ra) * K + k0 + ca * 8;
        CP_ASYNC16(sb + offa,        Ah + ga);
        CP_ASYNC16(sb + 8192 + offa, Al + ga);
        int rb = idx >> 4, cb = idx & 15;
        uint32_t offb = rb * 256 + ((cb ^ (rb & 7)) << 4);
        size_t gb = (size_t)(k0 + rb) * N + col0 + cb * 8;
        CP_ASYNC16(sb + 16384 + offb, Bh + gb);
        CP_ASYNC16(sb + 24576 + offb, Bl + gb);
    }
    CP_COMMIT();
}

extern __shared__ __align__(1024) char smem_raw[];

__global__ __launch_bounds__(256) void gemm_split_kernel(
    const __nv_bfloat16* __restrict__ Ah, const __nv_bfloat16* __restrict__ Al,
    const __nv_bfloat16* __restrict__ Bh, const __nv_bfloat16* __restrict__ Bl,
    float* __restrict__ C,
    __nv_bfloat16* __restrict__ Ch, __nv_bfloat16* __restrict__ Cl,
    int M, int N, int K, int mode)
{
    const int tid = threadIdx.x;
    const int warp = tid >> 5, lane = tid & 31;
    const int warpM = warp >> 2, warpN = warp & 3;
    const uint32_t smem_base = (uint32_t)__cvta_generic_to_shared(smem_raw);
    const int tiles_x = N >> 7;
    const int tiles = (M >> 7) * tiles_x;
    const int KT = K / 32;

    for (int t = blockIdx.x; t < tiles; t += gridDim.x) {
        const int row0 = (t / tiles_x) << 7;
        const int col0 = (t % tiles_x) << 7;

        __syncthreads();   // previous tile's smem fully consumed

        float acc[4][4][4];
        #pragma unroll
        for (int m = 0; m < 4; m++)
            #pragma unroll
            for (int n = 0; n < 4; n++)
                #pragma unroll
                for (int r = 0; r < 4; r++) acc[m][n][r] = 0.f;

        gemm_load_stage(smem_base,         tid, row0, col0, 0,  K, N, Ah, Al, Bh, Bl);
        gemm_load_stage(smem_base + 32768, tid, row0, col0, 32, K, N, Ah, Al, Bh, Bl);

        for (int kt = 0; kt < KT; kt++) {
            if (kt + 1 < KT) { CP_WAIT1(); } else { CP_WAIT0(); }
            __syncthreads();
            if (kt + 2 < KT)
                gemm_load_stage(smem_base + ((kt + 2) % 3) * 32768, tid,
                                row0, col0, (kt + 2) * 32, K, N, Ah, Al, Bh, Bl);
            const uint32_t sb = smem_base + (kt % 3) * 32768;

            #pragma unroll
            for (int ks = 0; ks < 2; ks++) {
                uint32_t bfr[2][4][2];
                const int rB = ks * 16 + (lane & 15);
                const int gB = lane >> 4;
                #pragma unroll
                for (int p = 0; p < 2; p++) {
                    #pragma unroll
                    for (int np = 0; np < 2; np++) {
                        const int chunk = warpN * 4 + np * 2 + gB;
                        uint32_t addr = sb + 16384 + p * 8192 + rB * 256
                                      + ((chunk ^ (rB & 7)) << 4);
                        asm volatile(
                            "ldmatrix.sync.aligned.m8n8.x4.trans.shared.b16 "
                            "{%0,%1,%2,%3}, [%4];"
                            : "=r"(bfr[p][np * 2][0]),     "=r"(bfr[p][np * 2][1]),
                              "=r"(bfr[p][np * 2 + 1][0]), "=r"(bfr[p][np * 2 + 1][1])
                            : "r"(addr));
                    }
                }
                #pragma unroll
                for (int m = 0; m < 4; m++) {
                    uint32_t afr[2][4];
                    const int rA = warpM * 64 + m * 16 + (lane & 15);
                    const int chA = ks * 2 + (lane >> 4);
                    #pragma unroll
                    for (int p = 0; p < 2; p++) {
                        uint32_t addr = sb + p * 8192 + rA * 64
                                      + ((chA ^ (rA & 3)) << 4);
                        asm volatile(
                            "ldmatrix.sync.aligned.m8n8.x4.shared.b16 {%0,%1,%2,%3}, [%4];"
                            : "=r"(afr[p][0]), "=r"(afr[p][1]),
                              "=r"(afr[p][2]), "=r"(afr[p][3]) : "r"(addr));
                    }
                    #pragma unroll
                    for (int n = 0; n < 4; n++) {
                        mma_bf16(acc[m][n], afr[0], bfr[0][n]);
                        mma_bf16(acc[m][n], afr[0], bfr[1][n]);
                        mma_bf16(acc[m][n], afr[1], bfr[0][n]);
                    }
                }
            }
        }

        #pragma unroll
        for (int m = 0; m < 4; m++) {
            #pragma unroll
            for (int n = 0; n < 4; n++) {
                const int r = row0 + warpM * 64 + m * 16 + (lane >> 2);
                const int c = col0 + warpN * 32 + n * 8 + (lane & 3) * 2;
                if (mode == 0) {
                    *(float2*)(C + (size_t)r * N + c) =
                        make_float2(acc[m][n][0], acc[m][n][1]);
                    *(float2*)(C + (size_t)(r + 8) * N + c) =
                        make_float2(acc[m][n][2], acc[m][n][3]);
                } else {
                    uint32_t h0, l0, h1, l1;
                    split_pack(acc[m][n][0], acc[m][n][1], h0, l0);
                    split_pack(acc[m][n][2], acc[m][n][3], h1, l1);
                    *(uint32_t*)(Ch + (size_t)r * N + c)       = h0;
                    *(uint32_t*)(Cl + (size_t)r * N + c)       = l0;
                    *(uint32_t*)(Ch + (size_t)(r + 8) * N + c) = h1;
                    *(uint32_t*)(Cl + (size_t)(r + 8) * N + c) = l1;
                }
            }
        }
    }
}

// ---------------------------------------------------------------------------
// Persistent tensor-core flash attention (causal), FULL 6-term numerics
// (round-10 known-good: rel_err 1.66e-5; both dropped-term variants fail):
//   scores = qh·kh + qh·kl + ql·kh
//   out    = ph·vh + pl·vh + ph·vl
// grid = 296, block = 128 (4 warps). Snake-scheduled heavy-first tiles.
// KV double-buffered (32KB stages: Kh@0 Kl@8K Vh@16K Vl@24K).
// smem: Qh[128][64] @0, Ql @16384, stages @32768 + s*32768.  96KB -> 2 CTA/SM.
// ---------------------------------------------------------------------------
__device__ __forceinline__ void attn_load_kv(
    uint32_t stage, int tid, int b, int h0, int j0,
    const __nv_bfloat16* __restrict__ qkvh,
    const __nv_bfloat16* __restrict__ qkvl)
{
    #pragma unroll
    for (int i = 0; i < 16; i++) {
        int idx = tid + i * 128;
        int field = idx >> 9;             // 0:Kh 1:Kl 2:Vh 3:Vl
        int rem = idx & 511;
        int r = rem >> 3, ch = rem & 7;
        const __nv_bfloat16* src = (field & 1) ? qkvl : qkvh;
        int col = ((field >> 1) ? 2048 : 1024) + h0 * 64 + ch * 8;
        const __nv_bfloat16* gp = src + ((size_t)(b * TT + j0 + r)) * 3072 + col;
        uint32_t off = stage + field * 8192 + r * 128 + ((ch ^ (r & 7)) << 4);
        CP_ASYNC16(off, gp);
    }
}

#define ATT_NT 512   // 16 q-blocks * 32 (b,h)

__global__ __launch_bounds__(128) void attn_mma_kernel(
    const __nv_bfloat16* __restrict__ qkvh,
    const __nv_bfloat16* __restrict__ qkvl,
    __nv_bfloat16* __restrict__ outh, __nv_bfloat16* __restrict__ outl)
{
    const int tid = threadIdx.x;
    const int warp = tid >> 5, lane = tid & 31;
    const uint32_t smem_base = (uint32_t)__cvta_generic_to_shared(smem_raw);
    const int G = gridDim.x;

    for (int p = 0;; p++) {
        const int rk = p * G + ((p & 1) ? (G - 1 - (int)blockIdx.x)
                                        : (int)blockIdx.x);
        if (rk >= ATT_NT) break;
        const int qb = 15 - (rk >> 5);
        const int bh = rk & 31;
        const int b = bh >> 4;
        const int h0 = bh & 15;
        const int qbase = qb * 128;

        __syncthreads();   // previous tile's smem fully consumed

        // --- Q tile (both planes) + first KV stages ---
        #pragma unroll
        for (int i = 0; i < 16; i++) {
            int idx = tid + i * 128;
            int plane = idx >> 10;
            int rem = idx & 1023;
            int r = rem >> 3, ch = rem & 7;
            const __nv_bfloat16* src = plane ? qkvl : qkvh;
            const __nv_bfloat16* gp =
                src + ((size_t)(b * TT + qbase + r)) * 3072 + h0 * 64 + ch * 8;
            uint32_t off = smem_base + plane * 16384 + r * 128
                         + ((ch ^ (r & 7)) << 4);
            CP_ASYNC16(off, gp);
        }
        const int nkb = 2 * (qb + 1);
        attn_load_kv(smem_base + 32768, tid, b, h0, 0, qkvh, qkvl);
        CP_COMMIT();
        if (nkb > 1) attn_load_kv(smem_base + 65536, tid, b, h0, 64, qkvh, qkvl);
        CP_COMMIT();

        uint32_t qf[2][2][4][4];
        float o[2][8][4];
        float mrow[2][2], lrow[2][2];
        #pragma unroll
        for (int m = 0; m < 2; m++) {
            #pragma unroll
            for (int n = 0; n < 8; n++)
                #pragma unroll
                for (int c = 0; c < 4; c++) o[m][n][c] = 0.f;
            mrow[m][0] = mrow[m][1] = -3.0e38f;
            lrow[m][0] = lrow[m][1] = 0.f;
        }

        const int rbase = qbase + warp * 32;

        for (int kb = 0; kb < nkb; kb++) {
            if (kb + 1 < nkb) { CP_WAIT1(); } else { CP_WAIT0(); }
            __syncthreads();

            if (kb == 0) {
                #pragma unroll
                for (int pp = 0; pp < 2; pp++)
                    #pragma unroll
                    for (int m = 0; m < 2; m++) {
                        const int rA = warp * 32 + m * 16 + (lane & 15);
                        #pragma unroll
                        for (int kt = 0; kt < 4; kt++) {
                            const int ch = kt * 2 + (lane >> 4);
                            uint32_t addr = smem_base + pp * 16384 + rA * 128
                                          + ((ch ^ (rA & 7)) << 4);
                            asm volatile(
                                "ldmatrix.sync.aligned.m8n8.x4.shared.b16 "
                                "{%0,%1,%2,%3}, [%4];"
                                : "=r"(qf[pp][m][kt][0]), "=r"(qf[pp][m][kt][1]),
                                  "=r"(qf[pp][m][kt][2]), "=r"(qf[pp][m][kt][3])
                                : "r"(addr));
                        }
                    }
            }

            const uint32_t sk = smem_base + 32768 + (kb & 1) * 32768;
            const int j0 = kb * 64;

            float acc[2][8][4];
            #pragma unroll
            for (int m = 0; m < 2; m++)
                #pragma unroll
                for (int n = 0; n < 8; n++)
                    #pragma unroll
                    for (int c = 0; c < 4; c++) acc[m][n][c] = 0.f;

            // ---- S = qh·Kh + qh·Kl + ql·Kh, x4 K loads (n-pairs) ----
            const int gK = lane >> 3;
            #pragma unroll
            for (int kt = 0; kt < 4; kt++) {
                #pragma unroll
                for (int np = 0; np < 4; np++) {
                    uint32_t kh[2][2], kl[2][2];
                    const int row = (np * 2 + (gK >> 1)) * 8 + (lane & 7);
                    const int ch = kt * 2 + (gK & 1);
                    uint32_t a0 = sk + row * 128 + ((ch ^ (row & 7)) << 4);
                    asm volatile(
                        "ldmatrix.sync.aligned.m8n8.x4.shared.b16 {%0,%1,%2,%3}, [%4];"
                        : "=r"(kh[0][0]), "=r"(kh[0][1]), "=r"(kh[1][0]), "=r"(kh[1][1])
                        : "r"(a0));
                    asm volatile(
                        "ldmatrix.sync.aligned.m8n8.x4.shared.b16 {%0,%1,%2,%3}, [%4];"
                        : "=r"(kl[0][0]), "=r"(kl[0][1]), "=r"(kl[1][0]), "=r"(kl[1][1])
                        : "r"(a0 + 8192));
                    #pragma unroll
                    for (int nn = 0; nn < 2; nn++) {
                        const int n = np * 2 + nn;
                        #pragma unroll
                        for (int m = 0; m < 2; m++) {
                            mma_bf16(acc[m][n], qf[0][m][kt], kh[nn]);
                            mma_bf16(acc[m][n], qf[0][m][kt], kl[nn]);
                            mma_bf16(acc[m][n], qf[1][m][kt], kh[nn]);
                        }
                    }
                }
            }

            const bool diag = (j0 >= qbase);
            #pragma unroll
            for (int m = 0; m < 2; m++)
                #pragma unroll
                for (int n = 0; n < 8; n++)
                    #pragma unroll
                    for (int c = 0; c < 4; c++) {
                        float v = acc[m][n][c] * 0.125f;
                        if (diag) {
                            int col = j0 + n * 8 + ((lane & 3) << 1) + (c & 1);
                            int row = rbase + m * 16 + (lane >> 2) + ((c >> 1) << 3);
                            if (col > row) v = -1e30f;
                        }
                        acc[m][n][c] = v;
                    }

            #pragma unroll
            for (int m = 0; m < 2; m++) {
                #pragma unroll
                for (int h = 0; h < 2; h++) {
                    float mt = mrow[m][h];
                    #pragma unroll
                    for (int n = 0; n < 8; n++)
                        mt = fmaxf(mt, fmaxf(acc[m][n][2 * h], acc[m][n][2 * h + 1]));
                    mt = fmaxf(mt, __shfl_xor_sync(0xffffffffu, mt, 1));
                    mt = fmaxf(mt, __shfl_xor_sync(0xffffffffu, mt, 2));
                    float rs = __expf(mrow[m][h] - mt);
                    mrow[m][h] = mt;
                    float lsum = 0.f;
                    #pragma unroll
                    for (int n = 0; n < 8; n++) {
                        float p0 = __expf(acc[m][n][2 * h]     - mt);
                        float p1 = __expf(acc[m][n][2 * h + 1] - mt);
                        acc[m][n][2 * h]     = p0;
                        acc[m][n][2 * h + 1] = p1;
                        lsum += p0 + p1;
                        o[m][n][2 * h]     *= rs;
                        o[m][n][2 * h + 1] *= rs;
                    }
                    lrow[m][h] = lrow[m][h] * rs + lsum;
                }
            }

            // ---- O += ph·Vh + pl·Vh + ph·Vl, x4.trans V loads (n-pairs) ----
            #pragma unroll
            for (int kt = 0; kt < 4; kt++) {
                uint32_t pah[2][4], pal[2][4];
                #pragma unroll
                for (int m = 0; m < 2; m++) {
                    split_pack(acc[m][2 * kt][0],     acc[m][2 * kt][1],     pah[m][0], pal[m][0]);
                    split_pack(acc[m][2 * kt][2],     acc[m][2 * kt][3],     pah[m][1], pal[m][1]);
                    split_pack(acc[m][2 * kt + 1][0], acc[m][2 * kt + 1][1], pah[m][2], pal[m][2]);
                    split_pack(acc[m][2 * kt + 1][2], acc[m][2 * kt + 1][3], pah[m][3], pal[m][3]);
                }
                const int rV = kt * 16 + (lane & 15);
                const int gV = lane >> 4;
                #pragma unroll
                for (int np = 0; np < 4; np++) {
                    uint32_t vh[2][2], vl[2][2];
                    const int ch = np * 2 + gV;
                    uint32_t a0 = sk + 16384 + rV * 128 + ((ch ^ (rV & 7)) << 4);
                    asm volatile(
                        "ldmatrix.sync.aligned.m8n8.x4.trans.shared.b16 {%0,%1,%2,%3}, [%4];"
                        : "=r"(vh[0][0]), "=r"(vh[0][1]), "=r"(vh[1][0]), "=r"(vh[1][1])
                        : "r"(a0));
                    asm volatile(
                        "ldmatrix.sync.aligned.m8n8.x4.trans.shared.b16 {%0,%1,%2,%3}, [%4];"
                        : "=r"(vl[0][0]), "=r"(vl[0][1]), "=r"(vl[1][0]), "=r"(vl[1][1])
                        : "r"(a0 + 8192));
                    #pragma unroll
                    for (int nn = 0; nn < 2; nn++) {
                        const int n = np * 2 + nn;
                        #pragma unroll
                        for (int m = 0; m < 2; m++) {
                            mma_bf16(o[m][n], pah[m], vh[nn]);
                            mma_bf16(o[m][n], pal[m], vh[nn]);
                            mma_bf16(o[m][n], pah[m], vl[nn]);
                        }
                    }
                }
            }

            __syncthreads();
            if (kb + 2 < nkb) {
                attn_load_kv(smem_base + 32768 + (kb & 1) * 32768, tid, b, h0,
                             (kb + 2) * 64, qkvh, qkvl);
                CP_COMMIT();
            }
        }

        float inv[2][2];
        #pragma unroll
        for (int m = 0; m < 2; m++)
            #pragma unroll
            for (int h = 0; h < 2; h++) {
                float lt = lrow[m][h];
                lt += __shfl_xor_sync(0xffffffffu, lt, 1);
                lt += __shfl_xor_sync(0xffffffffu, lt, 2);
                inv[m][h] = 1.f / lt;
            }

        #pragma unroll
        for (int m = 0; m < 2; m++) {
            const int r0 = rbase + m * 16 + (lane >> 2);
            #pragma unroll
            for (int n = 0; n < 8; n++) {
                const int cd = h0 * 64 + n * 8 + ((lane & 3) << 1);
                uint32_t h_, l_;
                split_pack(o[m][n][0] * inv[m][0], o[m][n][1] * inv[m][0], h_, l_);
                size_t base0 = (size_t)(b * TT + r0) * 1024 + cd;
                *(uint32_t*)(outh + base0) = h_;
                *(uint32_t*)(outl + base0) = l_;
                split_pack(o[m][n][2] * inv[m][1], o[m][n][3] * inv[m][1], h_, l_);
                size_t base1 = (size_t)(b * TT + r0 + 8) * 1024 + cd;
                *(uint32_t*)(outh + base1) = h_;
                *(uint32_t*)(outl + base1) = l_;
            }
        }
    }
}

// ---------------------------------------------------------------------------
extern "C" void kernel_launch(void* const* d_in, const int* in_sizes, int n_in,
                              void* d_out, int out_size)
{
    const float* x    = (const float*)d_in[0];
    const float* Wqkv = (const float*)d_in[1];
    const float* Wout = (const float*)d_in[2];
    float* out = (float*)d_out;

    __nv_bfloat16 *qkvh, *qkvl, *xh, *xl, *wqh, *wql, *woh, *wol, *ah, *al;
    cudaGetSymbolAddress((void**)&qkvh, g_qkvh); cudaGetSymbolAddress((void**)&qkvl, g_qkvl);
    cudaGetSymbolAddress((void**)&xh, g_xh);     cudaGetSymbolAddress((void**)&xl, g_xl);
    cudaGetSymbolAddress((void**)&wqh, g_wqh);   cudaGetSymbolAddress((void**)&wql, g_wql);
    cudaGetSymbolAddress((void**)&woh, g_woh);   cudaGetSymbolAddress((void**)&wol, g_wol);
    cudaGetSymbolAddress((void**)&ah, g_ah);     cudaGetSymbolAddress((void**)&al, g_al);

    cudaFuncSetAttribute(gemm_split_kernel,
                         cudaFuncAttributeMaxDynamicSharedMemorySize, 98304);
    cudaFuncSetAttribute(attn_mma_kernel,
                         cudaFuncAttributeMaxDynamicSharedMemorySize, 98304);

    const int M = TB * TT;            // 4096
    const int total4 = (NX + NWQ + NWO) / 4;

    // 0) fused input splits
    split3_kernel<<<(total4 + 255) / 256, 256>>>(x, Wqkv, Wout,
                                                 xh, xl, wqh, wql, woh, wol);

    // 1) QKV projection -> bf16 hi/lo planes (persistent, 768 tiles)
    {
        int tiles = (M / 128) * (3 * TC / 128);
        int grid = tiles < 296 ? tiles : 296;
        gemm_split_kernel<<<grid, 256, 98304>>>(
            xh, xl, wqh, wql, nullptr, qkvh, qkvl, M, 3 * TC, TC, 1);
    }

    // 2) Persistent causal flash attention -> bf16 hi/lo planes
    attn_mma_kernel<<<296, 128, 98304>>>(qkvh, qkvl, ah, al);

    // 3) Output projection -> fp32 out (256 tiles)
    {
        int tiles = (M / 128) * (TC / 128);
        int grid = tiles < 296 ? tiles : 296;
        gemm_split_kernel<<<grid, 256, 98304>>>(
            ah, al, woh, wol, out, nullptr, nullptr, M, TC, TC, 0);
    }
}